// round 12
// baseline (speedup 1.0000x reference)
#include <cuda_runtime.h>
#include <cuda_fp16.h>
#include <stdint.h>

// Problem dims (fixed)
#define MTOT   8192     // B*T
#define SEQ    2048
#define N1     8192     // 2*d_inner
#define K1     2048     // d_model
#define DINNER 4096
#define N2     2048     // d_model
#define K2     4096     // d_inner

// ---------------- scratch (device globals; no runtime alloc) ----------------
__device__ __half g_xproj[(size_t)MTOT * N1];     // 128 MB (fp16)
__device__ __half g_x_hi [(size_t)MTOT * K1];
__device__ __half g_wi_hi[(size_t)N1 * K1];
__device__ __half g_h_hi [(size_t)MTOT * K2];
__device__ __half g_wo_hi[(size_t)N2 * K2];

// ---------------- PTX helpers (legal on plain sm_103) ----------------
__device__ __forceinline__ uint32_t smem_u32(const void* p) {
    uint32_t a;
    asm("{ .reg .u64 t; cvta.to.shared.u64 t, %1; cvt.u32.u64 %0, t; }" : "=r"(a) : "l"(p));
    return a;
}
#define MBAR_INIT(a, c) \
    asm volatile("mbarrier.init.shared.b64 [%0], %1;" :: "r"(a), "r"(c) : "memory")
#define MBAR_EXPECT_TX(a, b) \
    asm volatile("mbarrier.arrive.expect_tx.shared.b64 _, [%0], %1;" :: "r"(a), "r"(b) : "memory")
#define MBAR_ARRIVE(a) \
    asm volatile("mbarrier.arrive.shared.b64 _, [%0];" :: "r"(a) : "memory")
#define MBAR_WAIT(a, ph) do {                                                      \
    uint32_t _m = (a), _p = (ph), _d;                                              \
    asm volatile("{ .reg .pred p; mbarrier.try_wait.parity.acquire.cta.shared::cta.b64 p, [%1], %2;" \
                 " selp.b32 %0, 1, 0, p; }" : "=r"(_d) : "r"(_m), "r"(_p) : "memory"); \
    if (!_d) {                                                                     \
        asm volatile("{ .reg .pred P;\n"                                           \
                     "W%=: mbarrier.try_wait.parity.acquire.cta.shared::cta.b64 P, [%0], %1, 0x989680;\n" \
                     "@P bra.uni D%=;\n bra.uni W%=;\nD%=: }"                      \
                     :: "r"(_m), "r"(_p) : "memory");                              \
    } } while (0)
#define BULK_G2S(sa, gp, bytes, mb) \
    asm volatile("cp.async.bulk.shared::cluster.global.mbarrier::complete_tx::bytes [%0], [%1], %2, [%3];" \
                 :: "r"(sa), "l"(gp), "r"(bytes), "r"(mb) : "memory")

__device__ __forceinline__ void ldsm_x4(uint32_t* r, uint32_t addr) {
    asm volatile("ldmatrix.sync.aligned.m8n8.x4.shared.b16 {%0,%1,%2,%3}, [%4];"
                 : "=r"(r[0]), "=r"(r[1]), "=r"(r[2]), "=r"(r[3]) : "r"(addr));
}
__device__ __forceinline__ void mma_f16(float* d, const uint32_t* a, const uint32_t* b) {
    asm volatile("mma.sync.aligned.m16n8k16.row.col.f32.f16.f16.f32 "
                 "{%0,%1,%2,%3},{%4,%5,%6,%7},{%8,%9},{%0,%1,%2,%3};"
                 : "+f"(d[0]), "+f"(d[1]), "+f"(d[2]), "+f"(d[3])
                 : "r"(a[0]), "r"(a[1]), "r"(a[2]), "r"(a[3]), "r"(b[0]), "r"(b[1]));
}

// fp16 tiled layout: 128 rows x 64 fp16 (16 KB) tiles, k-tile fastest, SW128 swizzle.
__device__ __forceinline__ size_t tiled_off(int r, int c, int K) {
    size_t tile = ((size_t)(r >> 7) * (size_t)(K >> 6) + (size_t)(c >> 6)) << 14;
    uint32_t off = ((uint32_t)(r & 127) << 7) | ((uint32_t)(c & 63) << 1);
    off ^= (off >> 3) & 0x70;
    return tile + off;
}

// ---------------- convert fp32 -> fp16 in tiled layout ----------------
__global__ void cvt_f16_tiled(const float* __restrict__ src, __half* __restrict__ hi,
                              int total8, int K, int kshift) {
    int idx = blockIdx.x * blockDim.x + threadIdx.x;
    if (idx >= total8) return;
    int e0 = idx << 3;
    int r = e0 >> kshift;
    int c = e0 & (K - 1);
    const float* p = src + (size_t)r * K + c;
    float4 v0 = *reinterpret_cast<const float4*>(p);
    float4 v1 = *reinterpret_cast<const float4*>(p + 4);
    float xs[8] = {v0.x, v0.y, v0.z, v0.w, v1.x, v1.y, v1.z, v1.w};
    __align__(16) __half hv[8];
#pragma unroll
    for (int j = 0; j < 8; j++) hv[j] = __float2half_rn(xs[j]);
    *reinterpret_cast<uint4*>((char*)hi + tiled_off(r, c, K)) = *reinterpret_cast<const uint4*>(hv);
}

// ------- depthwise causal conv(4) + SiLU gate (fp16 xproj in) -> fp16 tiled -------
__device__ __forceinline__ void ld8h(const __half* p, float* out) {
    uint4 raw = *reinterpret_cast<const uint4*>(p);
    const __half2* hp = reinterpret_cast<const __half2*>(&raw);
#pragma unroll
    for (int q = 0; q < 4; q++) {
        float2 f = __half22float2(hp[q]);
        out[2 * q] = f.x; out[2 * q + 1] = f.y;
    }
}

__global__ void conv_gate_f16(const __half* __restrict__ xp, const float* __restrict__ cw,
                              const float* __restrict__ cb, const float* __restrict__ Dv,
                              __half* __restrict__ hhi) {
    int idx = blockIdx.x * blockDim.x + threadIdx.x;
    if (idx >= (MTOT * DINNER) / 8) return;
    int d0 = (idx & 511) << 3;
    int m  = idx >> 9;
    int t  = m & (SEQ - 1);
    const __half* row = xp + (size_t)m * N1 + d0;

    float acc[8];
    {
        float4 b0 = *reinterpret_cast<const float4*>(cb + d0);
        float4 b1 = *reinterpret_cast<const float4*>(cb + d0 + 4);
        acc[0]=b0.x; acc[1]=b0.y; acc[2]=b0.z; acc[3]=b0.w;
        acc[4]=b1.x; acc[5]=b1.y; acc[6]=b1.z; acc[7]=b1.w;
    }
    float4 cwv[8];
#pragma unroll
    for (int e = 0; e < 8; e++) cwv[e] = *reinterpret_cast<const float4*>(cw + (size_t)(d0 + e) * 4);

#pragma unroll
    for (int j = 0; j < 4; j++) {
        if (t >= j) {
            float xv[8];
            ld8h(row - (size_t)j * N1, xv);
#pragma unroll
            for (int e = 0; e < 8; e++) {
                float w = (j == 0) ? cwv[e].w : (j == 1) ? cwv[e].z : (j == 2) ? cwv[e].y : cwv[e].x;
                acc[e] = fmaf(xv[e], w, acc[e]);
            }
        }
    }
    float gv[8];
    ld8h(row + DINNER, gv);
    float4 dv0 = *reinterpret_cast<const float4*>(Dv + d0);
    float4 dv1 = *reinterpret_cast<const float4*>(Dv + d0 + 4);
    float dv[8] = {dv0.x, dv0.y, dv0.z, dv0.w, dv1.x, dv1.y, dv1.z, dv1.w};

    __align__(16) __half hv[8];
#pragma unroll
    for (int e = 0; e < 8; e++) {
        float s1 = acc[e] / (1.f + __expf(-acc[e]));
        float s2 = gv[e] / (1.f + __expf(-gv[e]));
        hv[e] = __float2half_rn(s1 * dv[e] * s2);
    }
    *reinterpret_cast<uint4*>((char*)hhi + tiled_off(m, d0, K2)) = *reinterpret_cast<const uint4*>(hv);
}

// ---------------- fp16 HMMA GEMM: C[M,N] = A[M,K] * B[N,K]^T ----------------
// CTA tile 128x128, BK=64, 3-stage async pipeline (32 KB/stage), 2 CTAs/SM.
// 8 compute warps (warp tile 64x32) + 1 producer. Single-buffered fragments:
// 4 warps/SMSP hide the ldsm latency by cross-warp interleave.
#define TILE_BYTES  16384
#define STAGE_BYTES 32768      // A, B
#define NSTAGE      3
#define SMEM_REQ    (NSTAGE * STAGE_BYTES + 1024 + 128)

template <typename OutT>
__global__ void __launch_bounds__(288, 2)
gemm_f16(const __half* __restrict__ A, const __half* __restrict__ B,
         OutT* __restrict__ C, int M, int N, int K) {
    extern __shared__ char smem_raw[];
    uint32_t sbase = (smem_u32(smem_raw) + 1023) & ~1023u;
    const int tid = threadIdx.x, wid = tid >> 5, lane = tid & 31;
    const int m0 = blockIdx.y * 128, n0 = blockIdx.x * 128;
    const int KT = K >> 6;
    const uint32_t bar = sbase + NSTAGE * STAGE_BYTES;
    // bar + 8*s: full[s]   bar + 64 + 8*s: empty[s]

    if (tid == 0) {
#pragma unroll
        for (int s = 0; s < NSTAGE; s++) {
            MBAR_INIT(bar + 8 * s, 1);
            MBAR_INIT(bar + 64 + 8 * s, 8);
        }
    }
    __syncthreads();

    if (wid == 8) {
        if (lane == 0) {
            const char* pA = (const char*)A + ((size_t)(m0 >> 7) * KT << 14);
            const char* pB = (const char*)B + ((size_t)(n0 >> 7) * KT << 14);
            int s = 0, eph = 1;
            for (int i = 0; i < KT; i++) {
                MBAR_WAIT(bar + 64 + 8 * s, eph);
                MBAR_EXPECT_TX(bar + 8 * s, (uint32_t)STAGE_BYTES);
                uint32_t st = sbase + s * STAGE_BYTES;
                size_t ko = (size_t)i << 14;
                BULK_G2S(st,              pA + ko, TILE_BYTES, bar + 8 * s);
                BULK_G2S(st + TILE_BYTES, pB + ko, TILE_BYTES, bar + 8 * s);
                if (++s == NSTAGE) { s = 0; eph ^= 1; }
            }
        }
        return;
    }

    // ---- compute warps 0..7: warp tile 64(m) x 32(n) ----
    const int wm = wid >> 2, wn = wid & 3;

    // swizzle mask depends only on lane&7 (row bits 0-2) — single scalar.
    const uint32_t msk = (uint32_t)(lane & 7) << 4;
    // A frag i base offset = a_off0 + i*2048 (i*16 rows << 7)
    const uint32_t a_off0 = ((uint32_t)(wm * 64 + (lane & 15)) << 7) | (((uint32_t)lane >> 4) << 4);
    // B pair p base offset = b_off0 + p*2048
    const uint32_t b_off0 = ((uint32_t)(wn * 32 + ((lane >> 4) << 3) + (lane & 7)) << 7)
                          | ((((uint32_t)lane >> 3) & 1) << 4);

    float acc[4][4][4];
#pragma unroll
    for (int i = 0; i < 4; i++)
#pragma unroll
        for (int j = 0; j < 4; j++)
#pragma unroll
            for (int e = 0; e < 4; e++) acc[i][j][e] = 0.f;

    uint32_t ah[4][4], bh[4][2];

    int s = 0, fph = 0;
    for (int it = 0; it < KT; it++) {
        MBAR_WAIT(bar + 8 * s, fph);
        uint32_t sA = sbase + s * STAGE_BYTES;
        uint32_t sB = sA + TILE_BYTES;

#pragma unroll
        for (int ks = 0; ks < 4; ks++) {
            const uint32_t kb = (uint32_t)ks * 32;
#pragma unroll
            for (int i = 0; i < 4; i++)
                ldsm_x4(ah[i], sA + ((a_off0 + i * 2048 + kb) ^ msk));
#pragma unroll
            for (int p = 0; p < 2; p++) {
                uint32_t r[4];
                ldsm_x4(r, sB + ((b_off0 + p * 2048 + kb) ^ msk));
                bh[2 * p][0] = r[0]; bh[2 * p][1] = r[1];
                bh[2 * p + 1][0] = r[2]; bh[2 * p + 1][1] = r[3];
            }
#pragma unroll
            for (int i = 0; i < 4; i++)
#pragma unroll
                for (int j = 0; j < 4; j++)
                    mma_f16(acc[i][j], ah[i], bh[j]);
        }
        __syncwarp();
        if (lane == 0) MBAR_ARRIVE(bar + 64 + 8 * s);
        if (++s == NSTAGE) { s = 0; fph ^= 1; }
    }

    // ---- epilogue: fragment -> C (row-major) ----
    const int g_row = lane >> 2;
    const int g_col = (lane & 3) * 2;
#pragma unroll
    for (int i = 0; i < 4; i++) {
        size_t r0 = (size_t)m0 + wm * 64 + i * 16 + g_row;
#pragma unroll
        for (int j = 0; j < 4; j++) {
            int c = n0 + wn * 32 + j * 8 + g_col;
            if (sizeof(OutT) == 4) {
                float2 v0 = make_float2(acc[i][j][0], acc[i][j][1]);
                float2 v1 = make_float2(acc[i][j][2], acc[i][j][3]);
                *reinterpret_cast<float2*>((float*)C + r0 * N + c)       = v0;
                *reinterpret_cast<float2*>((float*)C + (r0 + 8) * N + c) = v1;
            } else {
                __half2 v0 = __floats2half2_rn(acc[i][j][0], acc[i][j][1]);
                __half2 v1 = __floats2half2_rn(acc[i][j][2], acc[i][j][3]);
                *reinterpret_cast<__half2*>((__half*)C + r0 * N + c)       = v0;
                *reinterpret_cast<__half2*>((__half*)C + (r0 + 8) * N + c) = v1;
            }
        }
    }
}

// ---------------- launch ----------------
extern "C" void kernel_launch(void* const* d_in, const int* in_sizes, int n_in,
                              void* d_out, int out_size) {
    const float* x      = (const float*)d_in[0];
    const float* w_in   = (const float*)d_in[1];
    const float* w_out  = (const float*)d_in[2];
    const float* conv_w = (const float*)d_in[3];
    const float* conv_b = (const float*)d_in[4];
    const float* Dvec   = (const float*)d_in[5];
    float* out = (float*)d_out;

    __half *xp, *xhi, *wihi, *hhi, *wohi;
    cudaGetSymbolAddress((void**)&xp,   g_xproj);
    cudaGetSymbolAddress((void**)&xhi,  g_x_hi);
    cudaGetSymbolAddress((void**)&wihi, g_wi_hi);
    cudaGetSymbolAddress((void**)&hhi,  g_h_hi);
    cudaGetSymbolAddress((void**)&wohi, g_wo_hi);

    cudaFuncSetAttribute(gemm_f16<__half>, cudaFuncAttributeMaxDynamicSharedMemorySize, SMEM_REQ);
    cudaFuncSetAttribute(gemm_f16<float>,  cudaFuncAttributeMaxDynamicSharedMemorySize, SMEM_REQ);

    // converts (tiled+swizzled fp16)
    {
        int t8 = MTOT * K1 / 8;
        cvt_f16_tiled<<<(t8 + 255) / 256, 256>>>(x, xhi, t8, K1, 11);
    }
    {
        int t8 = N1 * K1 / 8;
        cvt_f16_tiled<<<(t8 + 255) / 256, 256>>>(w_in, wihi, t8, K1, 11);
    }
    {
        int t8 = N2 * K2 / 8;
        cvt_f16_tiled<<<(t8 + 255) / 256, 256>>>(w_out, wohi, t8, K2, 12);
    }

    // GEMM1: xproj[8192,8192] (fp16) = x @ w_in^T
    gemm_f16<__half><<<dim3(N1 / 128, MTOT / 128), 288, SMEM_REQ>>>(xhi, wihi, xp, MTOT, N1, K1);

    // conv + gate -> h (fp16)
    {
        int t8 = MTOT * DINNER / 8;
        conv_gate_f16<<<(t8 + 255) / 256, 256>>>(xp, conv_w, conv_b, Dvec, hhi);
    }

    // GEMM2: out[8192,2048] (fp32) = h @ w_out^T
    gemm_f16<float><<<dim3(N2 / 128, MTOT / 128), 288, SMEM_REQ>>>(hhi, wohi, out, MTOT, N2, K2);
}

// round 13
// speedup vs baseline: 1.1704x; 1.1704x over previous
#include <cuda_runtime.h>
#include <cuda_fp16.h>
#include <stdint.h>

// Problem dims (fixed)
#define MTOT   8192     // B*T
#define SEQ    2048
#define N1     8192     // 2*d_inner
#define K1     2048     // d_model
#define DINNER 4096
#define N2     2048     // d_model
#define K2     4096     // d_inner

// ---------------- scratch (device globals; no runtime alloc) ----------------
__device__ __half g_xproj[(size_t)MTOT * N1];     // 128 MB (fp16)
__device__ __half g_x_hi [(size_t)MTOT * K1];
__device__ __half g_wi_hi[(size_t)N1 * K1];
__device__ __half g_h_hi [(size_t)MTOT * K2];
__device__ __half g_wo_hi[(size_t)N2 * K2];

// ---------------- PTX helpers (legal on plain sm_103) ----------------
__device__ __forceinline__ uint32_t smem_u32(const void* p) {
    uint32_t a;
    asm("{ .reg .u64 t; cvta.to.shared.u64 t, %1; cvt.u32.u64 %0, t; }" : "=r"(a) : "l"(p));
    return a;
}
#define MBAR_INIT(a, c) \
    asm volatile("mbarrier.init.shared.b64 [%0], %1;" :: "r"(a), "r"(c) : "memory")
#define MBAR_EXPECT_TX(a, b) \
    asm volatile("mbarrier.arrive.expect_tx.shared.b64 _, [%0], %1;" :: "r"(a), "r"(b) : "memory")
#define MBAR_ARRIVE(a) \
    asm volatile("mbarrier.arrive.shared.b64 _, [%0];" :: "r"(a) : "memory")
#define MBAR_WAIT(a, ph) do {                                                      \
    uint32_t _m = (a), _p = (ph), _d;                                              \
    asm volatile("{ .reg .pred p; mbarrier.try_wait.parity.acquire.cta.shared::cta.b64 p, [%1], %2;" \
                 " selp.b32 %0, 1, 0, p; }" : "=r"(_d) : "r"(_m), "r"(_p) : "memory"); \
    if (!_d) {                                                                     \
        asm volatile("{ .reg .pred P;\n"                                           \
                     "W%=: mbarrier.try_wait.parity.acquire.cta.shared::cta.b64 P, [%0], %1, 0x989680;\n" \
                     "@P bra.uni D%=;\n bra.uni W%=;\nD%=: }"                      \
                     :: "r"(_m), "r"(_p) : "memory");                              \
    } } while (0)
#define BULK_G2S(sa, gp, bytes, mb) \
    asm volatile("cp.async.bulk.shared::cluster.global.mbarrier::complete_tx::bytes [%0], [%1], %2, [%3];" \
                 :: "r"(sa), "l"(gp), "r"(bytes), "r"(mb) : "memory")

__device__ __forceinline__ void ldsm_x4(uint32_t* r, uint32_t addr) {
    asm volatile("ldmatrix.sync.aligned.m8n8.x4.shared.b16 {%0,%1,%2,%3}, [%4];"
                 : "=r"(r[0]), "=r"(r[1]), "=r"(r[2]), "=r"(r[3]) : "r"(addr));
}
__device__ __forceinline__ void mma_f16(float* d, const uint32_t* a, const uint32_t* b) {
    asm volatile("mma.sync.aligned.m16n8k16.row.col.f32.f16.f16.f32 "
                 "{%0,%1,%2,%3},{%4,%5,%6,%7},{%8,%9},{%0,%1,%2,%3};"
                 : "+f"(d[0]), "+f"(d[1]), "+f"(d[2]), "+f"(d[3])
                 : "r"(a[0]), "r"(a[1]), "r"(a[2]), "r"(a[3]), "r"(b[0]), "r"(b[1]));
}

// fp16 tiled layout: 128 rows x 64 fp16 (16 KB) tiles, k-tile fastest, SW128 swizzle.
__device__ __forceinline__ size_t tiled_off(int r, int c, int K) {
    size_t tile = ((size_t)(r >> 7) * (size_t)(K >> 6) + (size_t)(c >> 6)) << 14;
    uint32_t off = ((uint32_t)(r & 127) << 7) | ((uint32_t)(c & 63) << 1);
    off ^= (off >> 3) & 0x70;
    return tile + off;
}

// ---------------- convert fp32 -> fp16 in tiled layout ----------------
__global__ void cvt_f16_tiled(const float* __restrict__ src, __half* __restrict__ hi,
                              int total8, int K, int kshift) {
    int idx = blockIdx.x * blockDim.x + threadIdx.x;
    if (idx >= total8) return;
    int e0 = idx << 3;
    int r = e0 >> kshift;
    int c = e0 & (K - 1);
    const float* p = src + (size_t)r * K + c;
    float4 v0 = *reinterpret_cast<const float4*>(p);
    float4 v1 = *reinterpret_cast<const float4*>(p + 4);
    float xs[8] = {v0.x, v0.y, v0.z, v0.w, v1.x, v1.y, v1.z, v1.w};
    __align__(16) __half hv[8];
#pragma unroll
    for (int j = 0; j < 8; j++) hv[j] = __float2half_rn(xs[j]);
    *reinterpret_cast<uint4*>((char*)hi + tiled_off(r, c, K)) = *reinterpret_cast<const uint4*>(hv);
}

// ------- depthwise causal conv(4) + SiLU gate (fp16 xproj in) -> fp16 tiled -------
__device__ __forceinline__ void ld8h(const __half* p, float* out) {
    uint4 raw = *reinterpret_cast<const uint4*>(p);
    const __half2* hp = reinterpret_cast<const __half2*>(&raw);
#pragma unroll
    for (int q = 0; q < 4; q++) {
        float2 f = __half22float2(hp[q]);
        out[2 * q] = f.x; out[2 * q + 1] = f.y;
    }
}

__global__ void conv_gate_f16(const __half* __restrict__ xp, const float* __restrict__ cw,
                              const float* __restrict__ cb, const float* __restrict__ Dv,
                              __half* __restrict__ hhi) {
    int idx = blockIdx.x * blockDim.x + threadIdx.x;
    if (idx >= (MTOT * DINNER) / 8) return;
    int d0 = (idx & 511) << 3;
    int m  = idx >> 9;
    int t  = m & (SEQ - 1);
    const __half* row = xp + (size_t)m * N1 + d0;

    float acc[8];
    {
        float4 b0 = *reinterpret_cast<const float4*>(cb + d0);
        float4 b1 = *reinterpret_cast<const float4*>(cb + d0 + 4);
        acc[0]=b0.x; acc[1]=b0.y; acc[2]=b0.z; acc[3]=b0.w;
        acc[4]=b1.x; acc[5]=b1.y; acc[6]=b1.z; acc[7]=b1.w;
    }
    float4 cwv[8];
#pragma unroll
    for (int e = 0; e < 8; e++) cwv[e] = *reinterpret_cast<const float4*>(cw + (size_t)(d0 + e) * 4);

#pragma unroll
    for (int j = 0; j < 4; j++) {
        if (t >= j) {
            float xv[8];
            ld8h(row - (size_t)j * N1, xv);
#pragma unroll
            for (int e = 0; e < 8; e++) {
                float w = (j == 0) ? cwv[e].w : (j == 1) ? cwv[e].z : (j == 2) ? cwv[e].y : cwv[e].x;
                acc[e] = fmaf(xv[e], w, acc[e]);
            }
        }
    }
    float gv[8];
    ld8h(row + DINNER, gv);
    float4 dv0 = *reinterpret_cast<const float4*>(Dv + d0);
    float4 dv1 = *reinterpret_cast<const float4*>(Dv + d0 + 4);
    float dv[8] = {dv0.x, dv0.y, dv0.z, dv0.w, dv1.x, dv1.y, dv1.z, dv1.w};

    __align__(16) __half hv[8];
#pragma unroll
    for (int e = 0; e < 8; e++) {
        float s1 = acc[e] / (1.f + __expf(-acc[e]));
        float s2 = gv[e] / (1.f + __expf(-gv[e]));
        hv[e] = __float2half_rn(s1 * dv[e] * s2);
    }
    *reinterpret_cast<uint4*>((char*)hhi + tiled_off(m, d0, K2)) = *reinterpret_cast<const uint4*>(hv);
}

// ---------------- fp16 HMMA GEMM: C[M,N] = A[M,K] * B[N,K]^T ----------------
// CTA tile 128x128, BK=64, 4-stage async pipeline (32 KB/stage), 8 compute warps + 1 producer.
// Fragment double-buffering with cross-stage prefetch. k-step order is PHASE-SKEWED
// between warp halves (wm=0 starts at ks=0, wm=1 at ks=2) so the two consumer warps
// sharing an SMSP interleave ldsm and mma phases instead of running in lockstep.
#define TILE_BYTES  16384
#define STAGE_BYTES 32768      // A, B
#define NSTAGE      4
#define SMEM_REQ    (NSTAGE * STAGE_BYTES + 1024 + 128)

template <typename OutT>
__global__ void __launch_bounds__(288, 1)
gemm_f16(const __half* __restrict__ A, const __half* __restrict__ B,
         OutT* __restrict__ C, int M, int N, int K) {
    extern __shared__ char smem_raw[];
    uint32_t sbase = (smem_u32(smem_raw) + 1023) & ~1023u;
    const int tid = threadIdx.x, wid = tid >> 5, lane = tid & 31;
    const int m0 = blockIdx.y * 128, n0 = blockIdx.x * 128;
    const int KT = K >> 6;
    const uint32_t bar = sbase + NSTAGE * STAGE_BYTES;
    // bar + 8*s: full[s]   bar + 64 + 8*s: empty[s]

    if (tid == 0) {
#pragma unroll
        for (int s = 0; s < NSTAGE; s++) {
            MBAR_INIT(bar + 8 * s, 1);
            MBAR_INIT(bar + 64 + 8 * s, 8);
        }
    }
    __syncthreads();

    if (wid == 8) {
        if (lane == 0) {
            const char* pA = (const char*)A + ((size_t)(m0 >> 7) * KT << 14);
            const char* pB = (const char*)B + ((size_t)(n0 >> 7) * KT << 14);
            int eph[NSTAGE] = {1, 1, 1, 1};
            int s = 0;
            for (int i = 0; i < KT; i++) {
                MBAR_WAIT(bar + 64 + 8 * s, eph[s]);
                eph[s] ^= 1;
                MBAR_EXPECT_TX(bar + 8 * s, (uint32_t)STAGE_BYTES);
                uint32_t st = sbase + s * STAGE_BYTES;
                size_t ko = (size_t)i << 14;
                BULK_G2S(st,              pA + ko, TILE_BYTES, bar + 8 * s);
                BULK_G2S(st + TILE_BYTES, pB + ko, TILE_BYTES, bar + 8 * s);
                if (++s == NSTAGE) s = 0;
            }
        }
        return;
    }

    // ---- compute warps 0..7: warp tile 64(m) x 32(n) ----
    const int wm = wid >> 2, wn = wid & 3;
    const int kstart = 2 * wm;          // phase skew between SMSP warp pairs

    // swizzle mask depends only on lane&7 — provably uniform across frags/k-steps.
    const uint32_t msk = (uint32_t)(lane & 7) << 4;
    const uint32_t a_off0 = ((uint32_t)(wm * 64 + (lane & 15)) << 7) | (((uint32_t)lane >> 4) << 4);
    const uint32_t b_off0 = ((uint32_t)(wn * 32 + ((lane >> 4) << 3) + (lane & 7)) << 7)
                          | ((((uint32_t)lane >> 3) & 1) << 4);

    float acc[4][4][4];
#pragma unroll
    for (int i = 0; i < 4; i++)
#pragma unroll
        for (int j = 0; j < 4; j++)
#pragma unroll
            for (int e = 0; e < 4; e++) acc[i][j][e] = 0.f;

    // double-buffered fragments
    uint32_t ah[2][4][4], bh[2][4][2];

#define LOAD_FRAGS(buf, sA, sB, ks) do {                                           \
    uint32_t _kb = (uint32_t)(ks) * 32;                                            \
    _Pragma("unroll")                                                              \
    for (int _i = 0; _i < 4; _i++)                                                 \
        ldsm_x4(ah[buf][_i], (sA) + ((a_off0 + _i * 2048 + _kb) ^ msk));           \
    _Pragma("unroll")                                                              \
    for (int _p = 0; _p < 2; _p++) {                                               \
        uint32_t _r[4];                                                            \
        ldsm_x4(_r, (sB) + ((b_off0 + _p * 2048 + _kb) ^ msk));                    \
        bh[buf][2 * _p][0] = _r[0]; bh[buf][2 * _p][1] = _r[1];                    \
        bh[buf][2 * _p + 1][0] = _r[2]; bh[buf][2 * _p + 1][1] = _r[3];            \
    } } while (0)

    int fph[NSTAGE] = {0, 0, 0, 0};
    int s = 0;
    MBAR_WAIT(bar + 0, 0);
    fph[0] ^= 1;
    uint32_t sA = sbase, sB = sbase + TILE_BYTES;
    LOAD_FRAGS(0, sA, sB, kstart);

    for (int it = 0; it < KT; it++) {
        const int s2 = (s + 1 == NSTAGE) ? 0 : s + 1;
        uint32_t sA2 = sbase + s2 * STAGE_BYTES, sB2 = sA2 + TILE_BYTES;
#pragma unroll
        for (int ksi = 0; ksi < 4; ksi++) {
            const int cur = ksi & 1, nxt = cur ^ 1;
            if (ksi < 3) {
                LOAD_FRAGS(nxt, sA, sB, (kstart + ksi + 1) & 3);
            } else if (it + 1 < KT) {
                // cross-stage prefetch: wait for next stage, load its first frags
                MBAR_WAIT(bar + 8 * s2, fph[s2]);
                fph[s2] ^= 1;
                LOAD_FRAGS(nxt, sA2, sB2, kstart);
            }
#pragma unroll
            for (int i = 0; i < 4; i++)
#pragma unroll
                for (int j = 0; j < 4; j++)
                    mma_f16(acc[i][j], ah[cur][i], bh[cur][j]);
        }
        __syncwarp();
        if (lane == 0) MBAR_ARRIVE(bar + 64 + 8 * s);
        sA = sA2; sB = sB2;
        s = s2;
    }
#undef LOAD_FRAGS

    // ---- epilogue: fragment -> C (row-major) ----
    const int g_row = lane >> 2;
    const int g_col = (lane & 3) * 2;
#pragma unroll
    for (int i = 0; i < 4; i++) {
        size_t r0 = (size_t)m0 + wm * 64 + i * 16 + g_row;
#pragma unroll
        for (int j = 0; j < 4; j++) {
            int c = n0 + wn * 32 + j * 8 + g_col;
            if (sizeof(OutT) == 4) {
                float2 v0 = make_float2(acc[i][j][0], acc[i][j][1]);
                float2 v1 = make_float2(acc[i][j][2], acc[i][j][3]);
                *reinterpret_cast<float2*>((float*)C + r0 * N + c)       = v0;
                *reinterpret_cast<float2*>((float*)C + (r0 + 8) * N + c) = v1;
            } else {
                __half2 v0 = __floats2half2_rn(acc[i][j][0], acc[i][j][1]);
                __half2 v1 = __floats2half2_rn(acc[i][j][2], acc[i][j][3]);
                *reinterpret_cast<__half2*>((__half*)C + r0 * N + c)       = v0;
                *reinterpret_cast<__half2*>((__half*)C + (r0 + 8) * N + c) = v1;
            }
        }
    }
}

// ---------------- launch ----------------
extern "C" void kernel_launch(void* const* d_in, const int* in_sizes, int n_in,
                              void* d_out, int out_size) {
    const float* x      = (const float*)d_in[0];
    const float* w_in   = (const float*)d_in[1];
    const float* w_out  = (const float*)d_in[2];
    const float* conv_w = (const float*)d_in[3];
    const float* conv_b = (const float*)d_in[4];
    const float* Dvec   = (const float*)d_in[5];
    float* out = (float*)d_out;

    __half *xp, *xhi, *wihi, *hhi, *wohi;
    cudaGetSymbolAddress((void**)&xp,   g_xproj);
    cudaGetSymbolAddress((void**)&xhi,  g_x_hi);
    cudaGetSymbolAddress((void**)&wihi, g_wi_hi);
    cudaGetSymbolAddress((void**)&hhi,  g_h_hi);
    cudaGetSymbolAddress((void**)&wohi, g_wo_hi);

    cudaFuncSetAttribute(gemm_f16<__half>, cudaFuncAttributeMaxDynamicSharedMemorySize, SMEM_REQ);
    cudaFuncSetAttribute(gemm_f16<float>,  cudaFuncAttributeMaxDynamicSharedMemorySize, SMEM_REQ);

    // converts (tiled+swizzled fp16)
    {
        int t8 = MTOT * K1 / 8;
        cvt_f16_tiled<<<(t8 + 255) / 256, 256>>>(x, xhi, t8, K1, 11);
    }
    {
        int t8 = N1 * K1 / 8;
        cvt_f16_tiled<<<(t8 + 255) / 256, 256>>>(w_in, wihi, t8, K1, 11);
    }
    {
        int t8 = N2 * K2 / 8;
        cvt_f16_tiled<<<(t8 + 255) / 256, 256>>>(w_out, wohi, t8, K2, 12);
    }

    // GEMM1: xproj[8192,8192] (fp16) = x @ w_in^T
    gemm_f16<__half><<<dim3(N1 / 128, MTOT / 128), 288, SMEM_REQ>>>(xhi, wihi, xp, MTOT, N1, K1);

    // conv + gate -> h (fp16)
    {
        int t8 = MTOT * DINNER / 8;
        conv_gate_f16<<<(t8 + 255) / 256, 256>>>(xp, conv_w, conv_b, Dvec, hhi);
    }

    // GEMM2: out[8192,2048] (fp32) = h @ w_out^T
    gemm_f16<float><<<dim3(N2 / 128, MTOT / 128), 288, SMEM_REQ>>>(hhi, wohi, out, MTOT, N2, K2);
}

// round 14
// speedup vs baseline: 1.1942x; 1.0203x over previous
#include <cuda_runtime.h>
#include <cuda_fp16.h>
#include <stdint.h>

// Problem dims (fixed)
#define MTOT   8192     // B*T
#define SEQ    2048
#define N1     8192     // 2*d_inner
#define K1     2048     // d_model
#define DINNER 4096
#define N2     2048     // d_model
#define K2     4096     // d_inner

#define GRID_PERSIST 148

// ---------------- scratch (device globals; no runtime alloc) ----------------
__device__ __half g_xproj[(size_t)MTOT * N1];     // 128 MB (fp16)
__device__ __half g_x_hi [(size_t)MTOT * K1];
__device__ __half g_wi_hi[(size_t)N1 * K1];
__device__ __half g_h_hi [(size_t)MTOT * K2];
__device__ __half g_wo_hi[(size_t)N2 * K2];

// ---------------- PTX helpers (legal on plain sm_103) ----------------
__device__ __forceinline__ uint32_t smem_u32(const void* p) {
    uint32_t a;
    asm("{ .reg .u64 t; cvta.to.shared.u64 t, %1; cvt.u32.u64 %0, t; }" : "=r"(a) : "l"(p));
    return a;
}
#define MBAR_INIT(a, c) \
    asm volatile("mbarrier.init.shared.b64 [%0], %1;" :: "r"(a), "r"(c) : "memory")
#define MBAR_EXPECT_TX(a, b) \
    asm volatile("mbarrier.arrive.expect_tx.shared.b64 _, [%0], %1;" :: "r"(a), "r"(b) : "memory")
#define MBAR_ARRIVE(a) \
    asm volatile("mbarrier.arrive.shared.b64 _, [%0];" :: "r"(a) : "memory")
#define MBAR_WAIT(a, ph) do {                                                      \
    uint32_t _m = (a), _p = (ph), _d;                                              \
    asm volatile("{ .reg .pred p; mbarrier.try_wait.parity.acquire.cta.shared::cta.b64 p, [%1], %2;" \
                 " selp.b32 %0, 1, 0, p; }" : "=r"(_d) : "r"(_m), "r"(_p) : "memory"); \
    if (!_d) {                                                                     \
        asm volatile("{ .reg .pred P;\n"                                           \
                     "W%=: mbarrier.try_wait.parity.acquire.cta.shared::cta.b64 P, [%0], %1, 0x989680;\n" \
                     "@P bra.uni D%=;\n bra.uni W%=;\nD%=: }"                      \
                     :: "r"(_m), "r"(_p) : "memory");                              \
    } } while (0)
#define BULK_G2S(sa, gp, bytes, mb) \
    asm volatile("cp.async.bulk.shared::cluster.global.mbarrier::complete_tx::bytes [%0], [%1], %2, [%3];" \
                 :: "r"(sa), "l"(gp), "r"(bytes), "r"(mb) : "memory")

__device__ __forceinline__ void ldsm_x4(uint32_t* r, uint32_t addr) {
    asm volatile("ldmatrix.sync.aligned.m8n8.x4.shared.b16 {%0,%1,%2,%3}, [%4];"
                 : "=r"(r[0]), "=r"(r[1]), "=r"(r[2]), "=r"(r[3]) : "r"(addr));
}
__device__ __forceinline__ void mma_f16(float* d, const uint32_t* a, const uint32_t* b) {
    asm volatile("mma.sync.aligned.m16n8k16.row.col.f32.f16.f16.f32 "
                 "{%0,%1,%2,%3},{%4,%5,%6,%7},{%8,%9},{%0,%1,%2,%3};"
                 : "+f"(d[0]), "+f"(d[1]), "+f"(d[2]), "+f"(d[3])
                 : "r"(a[0]), "r"(a[1]), "r"(a[2]), "r"(a[3]), "r"(b[0]), "r"(b[1]));
}

// fp16 tiled layout: 128 rows x 64 fp16 (16 KB) tiles, k-tile fastest, SW128 swizzle.
__device__ __forceinline__ size_t tiled_off(int r, int c, int K) {
    size_t tile = ((size_t)(r >> 7) * (size_t)(K >> 6) + (size_t)(c >> 6)) << 14;
    uint32_t off = ((uint32_t)(r & 127) << 7) | ((uint32_t)(c & 63) << 1);
    off ^= (off >> 3) & 0x70;
    return tile + off;
}

// ---------------- convert fp32 -> fp16 in tiled layout ----------------
__global__ void cvt_f16_tiled(const float* __restrict__ src, __half* __restrict__ hi,
                              int total8, int K, int kshift) {
    int idx = blockIdx.x * blockDim.x + threadIdx.x;
    if (idx >= total8) return;
    int e0 = idx << 3;
    int r = e0 >> kshift;
    int c = e0 & (K - 1);
    const float* p = src + (size_t)r * K + c;
    float4 v0 = *reinterpret_cast<const float4*>(p);
    float4 v1 = *reinterpret_cast<const float4*>(p + 4);
    float xs[8] = {v0.x, v0.y, v0.z, v0.w, v1.x, v1.y, v1.z, v1.w};
    __align__(16) __half hv[8];
#pragma unroll
    for (int j = 0; j < 8; j++) hv[j] = __float2half_rn(xs[j]);
    *reinterpret_cast<uint4*>((char*)hi + tiled_off(r, c, K)) = *reinterpret_cast<const uint4*>(hv);
}

// ------- depthwise causal conv(4) + SiLU gate (fp16 xproj in) -> fp16 tiled -------
__device__ __forceinline__ void ld8h(const __half* p, float* out) {
    uint4 raw = *reinterpret_cast<const uint4*>(p);
    const __half2* hp = reinterpret_cast<const __half2*>(&raw);
#pragma unroll
    for (int q = 0; q < 4; q++) {
        float2 f = __half22float2(hp[q]);
        out[2 * q] = f.x; out[2 * q + 1] = f.y;
    }
}

__global__ void conv_gate_f16(const __half* __restrict__ xp, const float* __restrict__ cw,
                              const float* __restrict__ cb, const float* __restrict__ Dv,
                              __half* __restrict__ hhi) {
    int idx = blockIdx.x * blockDim.x + threadIdx.x;
    if (idx >= (MTOT * DINNER) / 8) return;
    int d0 = (idx & 511) << 3;
    int m  = idx >> 9;
    int t  = m & (SEQ - 1);
    const __half* row = xp + (size_t)m * N1 + d0;

    float acc[8];
    {
        float4 b0 = *reinterpret_cast<const float4*>(cb + d0);
        float4 b1 = *reinterpret_cast<const float4*>(cb + d0 + 4);
        acc[0]=b0.x; acc[1]=b0.y; acc[2]=b0.z; acc[3]=b0.w;
        acc[4]=b1.x; acc[5]=b1.y; acc[6]=b1.z; acc[7]=b1.w;
    }
    float4 cwv[8];
#pragma unroll
    for (int e = 0; e < 8; e++) cwv[e] = *reinterpret_cast<const float4*>(cw + (size_t)(d0 + e) * 4);

#pragma unroll
    for (int j = 0; j < 4; j++) {
        if (t >= j) {
            float xv[8];
            ld8h(row - (size_t)j * N1, xv);
#pragma unroll
            for (int e = 0; e < 8; e++) {
                float w = (j == 0) ? cwv[e].w : (j == 1) ? cwv[e].z : (j == 2) ? cwv[e].y : cwv[e].x;
                acc[e] = fmaf(xv[e], w, acc[e]);
            }
        }
    }
    float gv[8];
    ld8h(row + DINNER, gv);
    float4 dv0 = *reinterpret_cast<const float4*>(Dv + d0);
    float4 dv1 = *reinterpret_cast<const float4*>(Dv + d0 + 4);
    float dv[8] = {dv0.x, dv0.y, dv0.z, dv0.w, dv1.x, dv1.y, dv1.z, dv1.w};

    __align__(16) __half hv[8];
#pragma unroll
    for (int e = 0; e < 8; e++) {
        float s1 = acc[e] / (1.f + __expf(-acc[e]));
        float s2 = gv[e] / (1.f + __expf(-gv[e]));
        hv[e] = __float2half_rn(s1 * dv[e] * s2);
    }
    *reinterpret_cast<uint4*>((char*)hhi + tiled_off(m, d0, K2)) = *reinterpret_cast<const uint4*>(hv);
}

// ---------------- persistent fp16 HMMA GEMM: C[M,N] = A[M,K] * B[N,K]^T ----------------
// Grid = 148 persistent CTAs; each loops over 128x128 output tiles (stride = grid).
// BK=64, 4-stage async pipeline (32 KB/stage) runs WARM across tile boundaries:
// the consumer's cross-stage prefetch reaches into the next tile's first stage, so
// the epilogue of tile t overlaps the loads of tile t+1.
#define TILE_BYTES  16384
#define STAGE_BYTES 32768      // A, B
#define NSTAGE      4
#define SMEM_REQ    (NSTAGE * STAGE_BYTES + 1024 + 128)

template <typename OutT>
__global__ void __launch_bounds__(288, 1)
gemm_f16(const __half* __restrict__ A, const __half* __restrict__ B,
         OutT* __restrict__ C, int M, int N, int K) {
    extern __shared__ char smem_raw[];
    uint32_t sbase = (smem_u32(smem_raw) + 1023) & ~1023u;
    const int tid = threadIdx.x, wid = tid >> 5, lane = tid & 31;
    const int KT = K >> 6;
    const int nx = N >> 7;                    // n-tiles
    const int ntiles = (M >> 7) * nx;
    const int gridsz = gridDim.x;
    const uint32_t bar = sbase + NSTAGE * STAGE_BYTES;
    // bar + 8*s: full[s]   bar + 64 + 8*s: empty[s]

    if (tid == 0) {
#pragma unroll
        for (int s = 0; s < NSTAGE; s++) {
            MBAR_INIT(bar + 8 * s, 1);
            MBAR_INIT(bar + 64 + 8 * s, 8);
        }
    }
    __syncthreads();

    if (wid == 8) {
        if (lane == 0) {
            int eph[NSTAGE] = {1, 1, 1, 1};
            int s = 0;
            for (int tt = blockIdx.x; tt < ntiles; tt += gridsz) {
                const int mi = tt / nx, ni = tt % nx;
                const char* pA = (const char*)A + ((size_t)mi * KT << 14);
                const char* pB = (const char*)B + ((size_t)ni * KT << 14);
                for (int i = 0; i < KT; i++) {
                    MBAR_WAIT(bar + 64 + 8 * s, eph[s]);
                    eph[s] ^= 1;
                    MBAR_EXPECT_TX(bar + 8 * s, (uint32_t)STAGE_BYTES);
                    uint32_t st = sbase + s * STAGE_BYTES;
                    size_t ko = (size_t)i << 14;
                    BULK_G2S(st,              pA + ko, TILE_BYTES, bar + 8 * s);
                    BULK_G2S(st + TILE_BYTES, pB + ko, TILE_BYTES, bar + 8 * s);
                    if (++s == NSTAGE) s = 0;
                }
            }
        }
        return;
    }

    // ---- compute warps 0..7: warp tile 64(m) x 32(n) ----
    const int wm = wid >> 2, wn = wid & 3;

    // swizzle mask depends only on lane&7 — uniform across fragments and k-steps.
    const uint32_t msk = (uint32_t)(lane & 7) << 4;
    const uint32_t a_off0 = ((uint32_t)(wm * 64 + (lane & 15)) << 7) | (((uint32_t)lane >> 4) << 4);
    const uint32_t b_off0 = ((uint32_t)(wn * 32 + ((lane >> 4) << 3) + (lane & 7)) << 7)
                          | ((((uint32_t)lane >> 3) & 1) << 4);

    float acc[4][4][4];
#pragma unroll
    for (int i = 0; i < 4; i++)
#pragma unroll
        for (int j = 0; j < 4; j++)
#pragma unroll
            for (int e = 0; e < 4; e++) acc[i][j][e] = 0.f;

    // double-buffered fragments
    uint32_t ah[2][4][4], bh[2][4][2];

#define LOAD_FRAGS(buf, sA, sB, ks) do {                                           \
    uint32_t _kb = (uint32_t)(ks) * 32;                                            \
    _Pragma("unroll")                                                              \
    for (int _i = 0; _i < 4; _i++)                                                 \
        ldsm_x4(ah[buf][_i], (sA) + ((a_off0 + _i * 2048 + _kb) ^ msk));           \
    _Pragma("unroll")                                                              \
    for (int _p = 0; _p < 2; _p++) {                                               \
        uint32_t _r[4];                                                            \
        ldsm_x4(_r, (sB) + ((b_off0 + _p * 2048 + _kb) ^ msk));                    \
        bh[buf][2 * _p][0] = _r[0]; bh[buf][2 * _p][1] = _r[1];                    \
        bh[buf][2 * _p + 1][0] = _r[2]; bh[buf][2 * _p + 1][1] = _r[3];            \
    } } while (0)

    int fph[NSTAGE] = {0, 0, 0, 0};
    int s = 0;
    MBAR_WAIT(bar + 0, 0);
    fph[0] ^= 1;
    uint32_t sA = sbase, sB = sbase + TILE_BYTES;
    LOAD_FRAGS(0, sA, sB, 0);

    const int g_row = lane >> 2;
    const int g_col = (lane & 3) * 2;

    for (int tt = blockIdx.x; tt < ntiles; tt += gridsz) {
        const bool last_tile = (tt + gridsz >= ntiles);
        for (int it = 0; it < KT; it++) {
            const int s2 = (s + 1 == NSTAGE) ? 0 : s + 1;
            uint32_t sA2 = sbase + s2 * STAGE_BYTES, sB2 = sA2 + TILE_BYTES;
#pragma unroll
            for (int ks = 0; ks < 4; ks++) {
                const int cur = ks & 1, nxt = cur ^ 1;
                if (ks < 3) {
                    LOAD_FRAGS(nxt, sA, sB, ks + 1);
                } else if (it + 1 < KT || !last_tile) {
                    // cross-stage (and cross-tile) prefetch
                    MBAR_WAIT(bar + 8 * s2, fph[s2]);
                    fph[s2] ^= 1;
                    LOAD_FRAGS(nxt, sA2, sB2, 0);
                }
#pragma unroll
                for (int i = 0; i < 4; i++)
#pragma unroll
                    for (int j = 0; j < 4; j++)
                        mma_f16(acc[i][j], ah[cur][i], bh[cur][j]);
            }
            __syncwarp();
            if (lane == 0) MBAR_ARRIVE(bar + 64 + 8 * s);
            sA = sA2; sB = sB2;
            s = s2;
        }

        // ---- epilogue for this tile (overlaps next tile's TMA via pipeline) ----
        const int m0 = (tt / nx) * 128, n0 = (tt % nx) * 128;
#pragma unroll
        for (int i = 0; i < 4; i++) {
            size_t r0 = (size_t)m0 + wm * 64 + i * 16 + g_row;
#pragma unroll
            for (int j = 0; j < 4; j++) {
                int c = n0 + wn * 32 + j * 8 + g_col;
                if (sizeof(OutT) == 4) {
                    float2 v0 = make_float2(acc[i][j][0], acc[i][j][1]);
                    float2 v1 = make_float2(acc[i][j][2], acc[i][j][3]);
                    *reinterpret_cast<float2*>((float*)C + r0 * N + c)       = v0;
                    *reinterpret_cast<float2*>((float*)C + (r0 + 8) * N + c) = v1;
                } else {
                    __half2 v0 = __floats2half2_rn(acc[i][j][0], acc[i][j][1]);
                    __half2 v1 = __floats2half2_rn(acc[i][j][2], acc[i][j][3]);
                    *reinterpret_cast<__half2*>((__half*)C + r0 * N + c)       = v0;
                    *reinterpret_cast<__half2*>((__half*)C + (r0 + 8) * N + c) = v1;
                }
                acc[i][j][0] = 0.f; acc[i][j][1] = 0.f;
                acc[i][j][2] = 0.f; acc[i][j][3] = 0.f;
            }
        }
    }
#undef LOAD_FRAGS
}

// ---------------- launch ----------------
extern "C" void kernel_launch(void* const* d_in, const int* in_sizes, int n_in,
                              void* d_out, int out_size) {
    const float* x      = (const float*)d_in[0];
    const float* w_in   = (const float*)d_in[1];
    const float* w_out  = (const float*)d_in[2];
    const float* conv_w = (const float*)d_in[3];
    const float* conv_b = (const float*)d_in[4];
    const float* Dvec   = (const float*)d_in[5];
    float* out = (float*)d_out;

    __half *xp, *xhi, *wihi, *hhi, *wohi;
    cudaGetSymbolAddress((void**)&xp,   g_xproj);
    cudaGetSymbolAddress((void**)&xhi,  g_x_hi);
    cudaGetSymbolAddress((void**)&wihi, g_wi_hi);
    cudaGetSymbolAddress((void**)&hhi,  g_h_hi);
    cudaGetSymbolAddress((void**)&wohi, g_wo_hi);

    cudaFuncSetAttribute(gemm_f16<__half>, cudaFuncAttributeMaxDynamicSharedMemorySize, SMEM_REQ);
    cudaFuncSetAttribute(gemm_f16<float>,  cudaFuncAttributeMaxDynamicSharedMemorySize, SMEM_REQ);

    // converts (tiled+swizzled fp16)
    {
        int t8 = MTOT * K1 / 8;
        cvt_f16_tiled<<<(t8 + 255) / 256, 256>>>(x, xhi, t8, K1, 11);
    }
    {
        int t8 = N1 * K1 / 8;
        cvt_f16_tiled<<<(t8 + 255) / 256, 256>>>(w_in, wihi, t8, K1, 11);
    }
    {
        int t8 = N2 * K2 / 8;
        cvt_f16_tiled<<<(t8 + 255) / 256, 256>>>(w_out, wohi, t8, K2, 12);
    }

    // GEMM1: xproj[8192,8192] (fp16) = x @ w_in^T   (persistent)
    gemm_f16<__half><<<GRID_PERSIST, 288, SMEM_REQ>>>(xhi, wihi, xp, MTOT, N1, K1);

    // conv + gate -> h (fp16)
    {
        int t8 = MTOT * DINNER / 8;
        conv_gate_f16<<<(t8 + 255) / 256, 256>>>(xp, conv_w, conv_b, Dvec, hhi);
    }

    // GEMM2: out[8192,2048] (fp32) = h @ w_out^T   (persistent)
    gemm_f16<float><<<GRID_PERSIST, 288, SMEM_REQ>>>(hhi, wohi, out, MTOT, N2, K2);
}

// round 15
// speedup vs baseline: 1.2109x; 1.0140x over previous
#include <cuda_runtime.h>
#include <cuda_fp16.h>
#include <stdint.h>

// Problem dims (fixed)
#define MTOT   8192     // B*T
#define SEQ    2048
#define N1     8192     // 2*d_inner
#define K1     2048     // d_model
#define DINNER 4096
#define N2     2048     // d_model
#define K2     4096     // d_inner

#define GRID_PERSIST 148

// ---------------- scratch (device globals; no runtime alloc) ----------------
__device__ __half g_xproj[(size_t)MTOT * N1];     // 128 MB (fp16)
__device__ __half g_x_hi [(size_t)MTOT * K1];
__device__ __half g_wi_hi[(size_t)N1 * K1];
__device__ __half g_h_hi [(size_t)MTOT * K2];
__device__ __half g_wo_hi[(size_t)N2 * K2];

// ---------------- PTX helpers (legal on plain sm_103) ----------------
__device__ __forceinline__ uint32_t smem_u32(const void* p) {
    uint32_t a;
    asm("{ .reg .u64 t; cvta.to.shared.u64 t, %1; cvt.u32.u64 %0, t; }" : "=r"(a) : "l"(p));
    return a;
}
#define MBAR_INIT(a, c) \
    asm volatile("mbarrier.init.shared.b64 [%0], %1;" :: "r"(a), "r"(c) : "memory")
#define MBAR_EXPECT_TX(a, b) \
    asm volatile("mbarrier.arrive.expect_tx.shared.b64 _, [%0], %1;" :: "r"(a), "r"(b) : "memory")
#define MBAR_ARRIVE(a) \
    asm volatile("mbarrier.arrive.shared.b64 _, [%0];" :: "r"(a) : "memory")
#define MBAR_WAIT(a, ph) do {                                                      \
    uint32_t _m = (a), _p = (ph), _d;                                              \
    asm volatile("{ .reg .pred p; mbarrier.try_wait.parity.acquire.cta.shared::cta.b64 p, [%1], %2;" \
                 " selp.b32 %0, 1, 0, p; }" : "=r"(_d) : "r"(_m), "r"(_p) : "memory"); \
    if (!_d) {                                                                     \
        asm volatile("{ .reg .pred P;\n"                                           \
                     "W%=: mbarrier.try_wait.parity.acquire.cta.shared::cta.b64 P, [%0], %1, 0x989680;\n" \
                     "@P bra.uni D%=;\n bra.uni W%=;\nD%=: }"                      \
                     :: "r"(_m), "r"(_p) : "memory");                              \
    } } while (0)
#define BULK_G2S(sa, gp, bytes, mb) \
    asm volatile("cp.async.bulk.shared::cluster.global.mbarrier::complete_tx::bytes [%0], [%1], %2, [%3];" \
                 :: "r"(sa), "l"(gp), "r"(bytes), "r"(mb) : "memory")

__device__ __forceinline__ void ldsm_x4(uint32_t* r, uint32_t addr) {
    asm volatile("ldmatrix.sync.aligned.m8n8.x4.shared.b16 {%0,%1,%2,%3}, [%4];"
                 : "=r"(r[0]), "=r"(r[1]), "=r"(r[2]), "=r"(r[3]) : "r"(addr));
}
__device__ __forceinline__ void mma_f16(float* d, const uint32_t* a, const uint32_t* b) {
    asm volatile("mma.sync.aligned.m16n8k16.row.col.f32.f16.f16.f32 "
                 "{%0,%1,%2,%3},{%4,%5,%6,%7},{%8,%9},{%0,%1,%2,%3};"
                 : "+f"(d[0]), "+f"(d[1]), "+f"(d[2]), "+f"(d[3])
                 : "r"(a[0]), "r"(a[1]), "r"(a[2]), "r"(a[3]), "r"(b[0]), "r"(b[1]));
}

// fp16 tiled layout: 128 rows x 64 fp16 (16 KB) tiles, k-tile fastest, SW128 swizzle.
__device__ __forceinline__ size_t tiled_off(int r, int c, int K) {
    size_t tile = ((size_t)(r >> 7) * (size_t)(K >> 6) + (size_t)(c >> 6)) << 14;
    uint32_t off = ((uint32_t)(r & 127) << 7) | ((uint32_t)(c & 63) << 1);
    off ^= (off >> 3) & 0x70;
    return tile + off;
}

// ---------------- convert fp32 -> fp16 in tiled layout ----------------
__global__ void cvt_f16_tiled(const float* __restrict__ src, __half* __restrict__ hi,
                              int total8, int K, int kshift) {
    int idx = blockIdx.x * blockDim.x + threadIdx.x;
    if (idx >= total8) return;
    int e0 = idx << 3;
    int r = e0 >> kshift;
    int c = e0 & (K - 1);
    const float* p = src + (size_t)r * K + c;
    float4 v0 = *reinterpret_cast<const float4*>(p);
    float4 v1 = *reinterpret_cast<const float4*>(p + 4);
    float xs[8] = {v0.x, v0.y, v0.z, v0.w, v1.x, v1.y, v1.z, v1.w};
    __align__(16) __half hv[8];
#pragma unroll
    for (int j = 0; j < 8; j++) hv[j] = __float2half_rn(xs[j]);
    *reinterpret_cast<uint4*>((char*)hi + tiled_off(r, c, K)) = *reinterpret_cast<const uint4*>(hv);
}

// ------- depthwise causal conv(4) + SiLU gate (fp16 xproj in) -> fp16 tiled -------
// m-PAIRED: each thread computes outputs for (m, m+1) x 8 channels.
// Tap windows overlap -> 7x16B loads per 2 outputs instead of 10; weights loaded once.
__device__ __forceinline__ void ld8h(const __half* p, float* out) {
    uint4 raw = *reinterpret_cast<const uint4*>(p);
    const __half2* hp = reinterpret_cast<const __half2*>(&raw);
#pragma unroll
    for (int q = 0; q < 4; q++) {
        float2 f = __half22float2(hp[q]);
        out[2 * q] = f.x; out[2 * q + 1] = f.y;
    }
}

__global__ void conv_gate_f16(const __half* __restrict__ xp, const float* __restrict__ cw,
                              const float* __restrict__ cb, const float* __restrict__ Dv,
                              __half* __restrict__ hhi) {
    int idx = blockIdx.x * blockDim.x + threadIdx.x;
    if (idx >= (MTOT * DINNER) / 16) return;
    int d0 = (idx & 511) << 3;          // 8-channel group
    int m  = (idx >> 9) << 1;           // even m; (m, m+1) always in same batch
    int t  = m & (SEQ - 1);
    const __half* row = xp + (size_t)m * N1 + d0;

    // rows m-3 .. m+1 (guarded; zeros where out-of-batch)
    float x_m3[8] = {0,0,0,0,0,0,0,0}, x_m2[8] = {0,0,0,0,0,0,0,0}, x_m1[8] = {0,0,0,0,0,0,0,0};
    float x_m0[8], x_p1[8];
    ld8h(row, x_m0);
    ld8h(row + N1, x_p1);
    if (t >= 1) ld8h(row - (size_t)1 * N1, x_m1);
    if (t >= 2) ld8h(row - (size_t)2 * N1, x_m2);
    if (t >= 3) ld8h(row - (size_t)3 * N1, x_m3);

    // gates for m, m+1
    float g0[8], g1[8];
    ld8h(row + DINNER, g0);
    ld8h(row + DINNER + N1, g1);

    // weights (w0..w3 per channel), bias, D
    float4 cwv[8];
#pragma unroll
    for (int e = 0; e < 8; e++) cwv[e] = *reinterpret_cast<const float4*>(cw + (size_t)(d0 + e) * 4);
    float4 b0 = *reinterpret_cast<const float4*>(cb + d0);
    float4 b1 = *reinterpret_cast<const float4*>(cb + d0 + 4);
    float bias[8] = {b0.x, b0.y, b0.z, b0.w, b1.x, b1.y, b1.z, b1.w};
    float4 dv0 = *reinterpret_cast<const float4*>(Dv + d0);
    float4 dv1 = *reinterpret_cast<const float4*>(Dv + d0 + 4);
    float dv[8] = {dv0.x, dv0.y, dv0.z, dv0.w, dv1.x, dv1.y, dv1.z, dv1.w};

    __align__(16) __half hv0[8];
    __align__(16) __half hv1[8];
#pragma unroll
    for (int e = 0; e < 8; e++) {
        // output m:  x[m]*w3, x[m-1]*w2, x[m-2]*w1, x[m-3]*w0  (same order as before)
        float a0 = bias[e];
        a0 = fmaf(x_m0[e], cwv[e].w, a0);
        a0 = fmaf(x_m1[e], cwv[e].z, a0);
        a0 = fmaf(x_m2[e], cwv[e].y, a0);
        a0 = fmaf(x_m3[e], cwv[e].x, a0);
        // output m+1: x[m+1]*w3, x[m]*w2, x[m-1]*w1, x[m-2]*w0
        float a1 = bias[e];
        a1 = fmaf(x_p1[e], cwv[e].w, a1);
        a1 = fmaf(x_m0[e], cwv[e].z, a1);
        a1 = fmaf(x_m1[e], cwv[e].y, a1);
        a1 = fmaf(x_m2[e], cwv[e].x, a1);

        float s0 = a0 / (1.f + __expf(-a0));
        float s1 = a1 / (1.f + __expf(-a1));
        float q0 = g0[e] / (1.f + __expf(-g0[e]));
        float q1 = g1[e] / (1.f + __expf(-g1[e]));
        hv0[e] = __float2half_rn(s0 * dv[e] * q0);
        hv1[e] = __float2half_rn(s1 * dv[e] * q1);
    }
    *reinterpret_cast<uint4*>((char*)hhi + tiled_off(m,     d0, K2)) = *reinterpret_cast<const uint4*>(hv0);
    *reinterpret_cast<uint4*>((char*)hhi + tiled_off(m + 1, d0, K2)) = *reinterpret_cast<const uint4*>(hv1);
}

// ---------------- persistent fp16 HMMA GEMM: C[M,N] = A[M,K] * B[N,K]^T ----------------
// Grid = 148 persistent CTAs; warm 4-stage pipeline across tile boundaries.
#define TILE_BYTES  16384
#define STAGE_BYTES 32768      // A, B
#define NSTAGE      4
#define SMEM_REQ    (NSTAGE * STAGE_BYTES + 1024 + 128)

template <typename OutT>
__global__ void __launch_bounds__(288, 1)
gemm_f16(const __half* __restrict__ A, const __half* __restrict__ B,
         OutT* __restrict__ C, int M, int N, int K) {
    extern __shared__ char smem_raw[];
    uint32_t sbase = (smem_u32(smem_raw) + 1023) & ~1023u;
    const int tid = threadIdx.x, wid = tid >> 5, lane = tid & 31;
    const int KT = K >> 6;
    const int nx = N >> 7;
    const int ntiles = (M >> 7) * nx;
    const int gridsz = gridDim.x;
    const uint32_t bar = sbase + NSTAGE * STAGE_BYTES;

    if (tid == 0) {
#pragma unroll
        for (int s = 0; s < NSTAGE; s++) {
            MBAR_INIT(bar + 8 * s, 1);
            MBAR_INIT(bar + 64 + 8 * s, 8);
        }
    }
    __syncthreads();

    if (wid == 8) {
        if (lane == 0) {
            int eph[NSTAGE] = {1, 1, 1, 1};
            int s = 0;
            for (int tt = blockIdx.x; tt < ntiles; tt += gridsz) {
                const int mi = tt / nx, ni = tt % nx;
                const char* pA = (const char*)A + ((size_t)mi * KT << 14);
                const char* pB = (const char*)B + ((size_t)ni * KT << 14);
                for (int i = 0; i < KT; i++) {
                    MBAR_WAIT(bar + 64 + 8 * s, eph[s]);
                    eph[s] ^= 1;
                    MBAR_EXPECT_TX(bar + 8 * s, (uint32_t)STAGE_BYTES);
                    uint32_t st = sbase + s * STAGE_BYTES;
                    size_t ko = (size_t)i << 14;
                    BULK_G2S(st,              pA + ko, TILE_BYTES, bar + 8 * s);
                    BULK_G2S(st + TILE_BYTES, pB + ko, TILE_BYTES, bar + 8 * s);
                    if (++s == NSTAGE) s = 0;
                }
            }
        }
        return;
    }

    // ---- compute warps 0..7: warp tile 64(m) x 32(n) ----
    const int wm = wid >> 2, wn = wid & 3;

    const uint32_t msk = (uint32_t)(lane & 7) << 4;
    const uint32_t a_off0 = ((uint32_t)(wm * 64 + (lane & 15)) << 7) | (((uint32_t)lane >> 4) << 4);
    const uint32_t b_off0 = ((uint32_t)(wn * 32 + ((lane >> 4) << 3) + (lane & 7)) << 7)
                          | ((((uint32_t)lane >> 3) & 1) << 4);

    float acc[4][4][4];
#pragma unroll
    for (int i = 0; i < 4; i++)
#pragma unroll
        for (int j = 0; j < 4; j++)
#pragma unroll
            for (int e = 0; e < 4; e++) acc[i][j][e] = 0.f;

    uint32_t ah[2][4][4], bh[2][4][2];

#define LOAD_FRAGS(buf, sA, sB, ks) do {                                           \
    uint32_t _kb = (uint32_t)(ks) * 32;                                            \
    _Pragma("unroll")                                                              \
    for (int _i = 0; _i < 4; _i++)                                                 \
        ldsm_x4(ah[buf][_i], (sA) + ((a_off0 + _i * 2048 + _kb) ^ msk));           \
    _Pragma("unroll")                                                              \
    for (int _p = 0; _p < 2; _p++) {                                               \
        uint32_t _r[4];                                                            \
        ldsm_x4(_r, (sB) + ((b_off0 + _p * 2048 + _kb) ^ msk));                    \
        bh[buf][2 * _p][0] = _r[0]; bh[buf][2 * _p][1] = _r[1];                    \
        bh[buf][2 * _p + 1][0] = _r[2]; bh[buf][2 * _p + 1][1] = _r[3];            \
    } } while (0)

    int fph[NSTAGE] = {0, 0, 0, 0};
    int s = 0;
    MBAR_WAIT(bar + 0, 0);
    fph[0] ^= 1;
    uint32_t sA = sbase, sB = sbase + TILE_BYTES;
    LOAD_FRAGS(0, sA, sB, 0);

    const int g_row = lane >> 2;
    const int g_col = (lane & 3) * 2;

    for (int tt = blockIdx.x; tt < ntiles; tt += gridsz) {
        const bool last_tile = (tt + gridsz >= ntiles);
        for (int it = 0; it < KT; it++) {
            const int s2 = (s + 1 == NSTAGE) ? 0 : s + 1;
            uint32_t sA2 = sbase + s2 * STAGE_BYTES, sB2 = sA2 + TILE_BYTES;
#pragma unroll
            for (int ks = 0; ks < 4; ks++) {
                const int cur = ks & 1, nxt = cur ^ 1;
                if (ks < 3) {
                    LOAD_FRAGS(nxt, sA, sB, ks + 1);
                } else if (it + 1 < KT || !last_tile) {
                    MBAR_WAIT(bar + 8 * s2, fph[s2]);
                    fph[s2] ^= 1;
                    LOAD_FRAGS(nxt, sA2, sB2, 0);
                }
#pragma unroll
                for (int i = 0; i < 4; i++)
#pragma unroll
                    for (int j = 0; j < 4; j++)
                        mma_f16(acc[i][j], ah[cur][i], bh[cur][j]);
            }
            __syncwarp();
            if (lane == 0) MBAR_ARRIVE(bar + 64 + 8 * s);
            sA = sA2; sB = sB2;
            s = s2;
        }

        // ---- epilogue for this tile (overlaps next tile's TMA via pipeline) ----
        const int m0 = (tt / nx) * 128, n0 = (tt % nx) * 128;
#pragma unroll
        for (int i = 0; i < 4; i++) {
            size_t r0 = (size_t)m0 + wm * 64 + i * 16 + g_row;
#pragma unroll
            for (int j = 0; j < 4; j++) {
                int c = n0 + wn * 32 + j * 8 + g_col;
                if (sizeof(OutT) == 4) {
                    float2 v0 = make_float2(acc[i][j][0], acc[i][j][1]);
                    float2 v1 = make_float2(acc[i][j][2], acc[i][j][3]);
                    *reinterpret_cast<float2*>((float*)C + r0 * N + c)       = v0;
                    *reinterpret_cast<float2*>((float*)C + (r0 + 8) * N + c) = v1;
                } else {
                    __half2 v0 = __floats2half2_rn(acc[i][j][0], acc[i][j][1]);
                    __half2 v1 = __floats2half2_rn(acc[i][j][2], acc[i][j][3]);
                    *reinterpret_cast<__half2*>((__half*)C + r0 * N + c)       = v0;
                    *reinterpret_cast<__half2*>((__half*)C + (r0 + 8) * N + c) = v1;
                }
                acc[i][j][0] = 0.f; acc[i][j][1] = 0.f;
                acc[i][j][2] = 0.f; acc[i][j][3] = 0.f;
            }
        }
    }
#undef LOAD_FRAGS
}

// ---------------- launch ----------------
extern "C" void kernel_launch(void* const* d_in, const int* in_sizes, int n_in,
                              void* d_out, int out_size) {
    const float* x      = (const float*)d_in[0];
    const float* w_in   = (const float*)d_in[1];
    const float* w_out  = (const float*)d_in[2];
    const float* conv_w = (const float*)d_in[3];
    const float* conv_b = (const float*)d_in[4];
    const float* Dvec   = (const float*)d_in[5];
    float* out = (float*)d_out;

    __half *xp, *xhi, *wihi, *hhi, *wohi;
    cudaGetSymbolAddress((void**)&xp,   g_xproj);
    cudaGetSymbolAddress((void**)&xhi,  g_x_hi);
    cudaGetSymbolAddress((void**)&wihi, g_wi_hi);
    cudaGetSymbolAddress((void**)&hhi,  g_h_hi);
    cudaGetSymbolAddress((void**)&wohi, g_wo_hi);

    cudaFuncSetAttribute(gemm_f16<__half>, cudaFuncAttributeMaxDynamicSharedMemorySize, SMEM_REQ);
    cudaFuncSetAttribute(gemm_f16<float>,  cudaFuncAttributeMaxDynamicSharedMemorySize, SMEM_REQ);

    // converts (tiled+swizzled fp16)
    {
        int t8 = MTOT * K1 / 8;
        cvt_f16_tiled<<<(t8 + 255) / 256, 256>>>(x, xhi, t8, K1, 11);
    }
    {
        int t8 = N1 * K1 / 8;
        cvt_f16_tiled<<<(t8 + 255) / 256, 256>>>(w_in, wihi, t8, K1, 11);
    }
    {
        int t8 = N2 * K2 / 8;
        cvt_f16_tiled<<<(t8 + 255) / 256, 256>>>(w_out, wohi, t8, K2, 12);
    }

    // GEMM1: xproj[8192,8192] (fp16) = x @ w_in^T   (persistent)
    gemm_f16<__half><<<GRID_PERSIST, 288, SMEM_REQ>>>(xhi, wihi, xp, MTOT, N1, K1);

    // conv + gate -> h (fp16, m-paired)
    {
        int t16 = MTOT * DINNER / 16;
        conv_gate_f16<<<(t16 + 255) / 256, 256>>>(xp, conv_w, conv_b, Dvec, hhi);
    }

    // GEMM2: out[8192,2048] (fp32) = h @ w_out^T   (persistent)
    gemm_f16<float><<<GRID_PERSIST, 288, SMEM_REQ>>>(hhi, wohi, out, MTOT, N2, K2);
}

// round 16
// speedup vs baseline: 1.2278x; 1.0140x over previous
#include <cuda_runtime.h>
#include <cuda_fp16.h>
#include <stdint.h>

// Problem dims (fixed)
#define MTOT   8192     // B*T
#define SEQ    2048
#define N1     8192     // 2*d_inner
#define K1     2048     // d_model
#define DINNER 4096
#define N2     2048     // d_model
#define K2     4096     // d_inner

#define GRID_PERSIST 148
#define MWALK 16        // m-steps per conv thread (divides SEQ)

// ---------------- scratch (device globals; no runtime alloc) ----------------
__device__ __half g_xproj[(size_t)MTOT * N1];     // 128 MB (fp16)
__device__ __half g_x_hi [(size_t)MTOT * K1];
__device__ __half g_wi_hi[(size_t)N1 * K1];
__device__ __half g_h_hi [(size_t)MTOT * K2];
__device__ __half g_wo_hi[(size_t)N2 * K2];

// ---------------- PTX helpers (legal on plain sm_103) ----------------
__device__ __forceinline__ uint32_t smem_u32(const void* p) {
    uint32_t a;
    asm("{ .reg .u64 t; cvta.to.shared.u64 t, %1; cvt.u32.u64 %0, t; }" : "=r"(a) : "l"(p));
    return a;
}
#define MBAR_INIT(a, c) \
    asm volatile("mbarrier.init.shared.b64 [%0], %1;" :: "r"(a), "r"(c) : "memory")
#define MBAR_EXPECT_TX(a, b) \
    asm volatile("mbarrier.arrive.expect_tx.shared.b64 _, [%0], %1;" :: "r"(a), "r"(b) : "memory")
#define MBAR_ARRIVE(a) \
    asm volatile("mbarrier.arrive.shared.b64 _, [%0];" :: "r"(a) : "memory")
#define MBAR_WAIT(a, ph) do {                                                      \
    uint32_t _m = (a), _p = (ph), _d;                                              \
    asm volatile("{ .reg .pred p; mbarrier.try_wait.parity.acquire.cta.shared::cta.b64 p, [%1], %2;" \
                 " selp.b32 %0, 1, 0, p; }" : "=r"(_d) : "r"(_m), "r"(_p) : "memory"); \
    if (!_d) {                                                                     \
        asm volatile("{ .reg .pred P;\n"                                           \
                     "W%=: mbarrier.try_wait.parity.acquire.cta.shared::cta.b64 P, [%0], %1, 0x989680;\n" \
                     "@P bra.uni D%=;\n bra.uni W%=;\nD%=: }"                      \
                     :: "r"(_m), "r"(_p) : "memory");                              \
    } } while (0)
#define BULK_G2S(sa, gp, bytes, mb) \
    asm volatile("cp.async.bulk.shared::cluster.global.mbarrier::complete_tx::bytes [%0], [%1], %2, [%3];" \
                 :: "r"(sa), "l"(gp), "r"(bytes), "r"(mb) : "memory")

__device__ __forceinline__ void ldsm_x4(uint32_t* r, uint32_t addr) {
    asm volatile("ldmatrix.sync.aligned.m8n8.x4.shared.b16 {%0,%1,%2,%3}, [%4];"
                 : "=r"(r[0]), "=r"(r[1]), "=r"(r[2]), "=r"(r[3]) : "r"(addr));
}
__device__ __forceinline__ void mma_f16(float* d, const uint32_t* a, const uint32_t* b) {
    asm volatile("mma.sync.aligned.m16n8k16.row.col.f32.f16.f16.f32 "
                 "{%0,%1,%2,%3},{%4,%5,%6,%7},{%8,%9},{%0,%1,%2,%3};"
                 : "+f"(d[0]), "+f"(d[1]), "+f"(d[2]), "+f"(d[3])
                 : "r"(a[0]), "r"(a[1]), "r"(a[2]), "r"(a[3]), "r"(b[0]), "r"(b[1]));
}

// fp16 tiled layout: 128 rows x 64 fp16 (16 KB) tiles, k-tile fastest, SW128 swizzle.
__device__ __forceinline__ size_t tiled_off(int r, int c, int K) {
    size_t tile = ((size_t)(r >> 7) * (size_t)(K >> 6) + (size_t)(c >> 6)) << 14;
    uint32_t off = ((uint32_t)(r & 127) << 7) | ((uint32_t)(c & 63) << 1);
    off ^= (off >> 3) & 0x70;
    return tile + off;
}

// ---------------- convert fp32 -> fp16 in tiled layout ----------------
__global__ void cvt_f16_tiled(const float* __restrict__ src, __half* __restrict__ hi,
                              int total8, int K, int kshift) {
    int idx = blockIdx.x * blockDim.x + threadIdx.x;
    if (idx >= total8) return;
    int e0 = idx << 3;
    int r = e0 >> kshift;
    int c = e0 & (K - 1);
    const float* p = src + (size_t)r * K + c;
    float4 v0 = *reinterpret_cast<const float4*>(p);
    float4 v1 = *reinterpret_cast<const float4*>(p + 4);
    float xs[8] = {v0.x, v0.y, v0.z, v0.w, v1.x, v1.y, v1.z, v1.w};
    __align__(16) __half hv[8];
#pragma unroll
    for (int j = 0; j < 8; j++) hv[j] = __float2half_rn(xs[j]);
    *reinterpret_cast<uint4*>((char*)hi + tiled_off(r, c, K)) = *reinterpret_cast<const uint4*>(hv);
}

// ------- depthwise causal conv(4) + SiLU gate (fp16 xproj in) -> fp16 tiled -------
// m-WALKING: each thread keeps 8 channels and walks MWALK consecutive m values.
// Conv taps live in a rolling register window: per m only 1 new x load + 1 gate load.
// Weights/bias/D amortize over the walk. fma order per output kept identical.
__device__ __forceinline__ void ld8h(const __half* p, float* out) {
    uint4 raw = *reinterpret_cast<const uint4*>(p);
    const __half2* hp = reinterpret_cast<const __half2*>(&raw);
#pragma unroll
    for (int q = 0; q < 4; q++) {
        float2 f = __half22float2(hp[q]);
        out[2 * q] = f.x; out[2 * q + 1] = f.y;
    }
}

__global__ void conv_gate_f16(const __half* __restrict__ xp, const float* __restrict__ cw,
                              const float* __restrict__ cb, const float* __restrict__ Dv,
                              __half* __restrict__ hhi) {
    int idx = blockIdx.x * blockDim.x + threadIdx.x;
    if (idx >= (MTOT / MWALK) * (DINNER / 8)) return;
    const int d0 = (idx & 511) << 3;          // 8-channel group (DINNER/8 = 512)
    const int m0 = (idx >> 9) * MWALK;        // walk start (multiple of 16; SEQ%16==0)
    const int t0 = m0 & (SEQ - 1);
    const __half* row = xp + (size_t)m0 * N1 + d0;

    // constants for the walk
    float4 cwv[8];
#pragma unroll
    for (int e = 0; e < 8; e++) cwv[e] = *reinterpret_cast<const float4*>(cw + (size_t)(d0 + e) * 4);
    float4 b0 = *reinterpret_cast<const float4*>(cb + d0);
    float4 b1 = *reinterpret_cast<const float4*>(cb + d0 + 4);
    float bias[8] = {b0.x, b0.y, b0.z, b0.w, b1.x, b1.y, b1.z, b1.w};
    float4 dv0 = *reinterpret_cast<const float4*>(Dv + d0);
    float4 dv1 = *reinterpret_cast<const float4*>(Dv + d0 + 4);
    float dv[8] = {dv0.x, dv0.y, dv0.z, dv0.w, dv1.x, dv1.y, dv1.z, dv1.w};

    // rolling tap window: xm1 = x[m-1], xm2 = x[m-2], xm3 = x[m-3]
    float xm1[8] = {0,0,0,0,0,0,0,0};
    float xm2[8] = {0,0,0,0,0,0,0,0};
    float xm3[8] = {0,0,0,0,0,0,0,0};
    if (t0 >= 1) ld8h(row - (size_t)1 * N1, xm1);
    if (t0 >= 2) ld8h(row - (size_t)2 * N1, xm2);
    if (t0 >= 3) ld8h(row - (size_t)3 * N1, xm3);

#pragma unroll 4
    for (int step = 0; step < MWALK; step++) {
        float xm0[8], gv[8];
        ld8h(row, xm0);
        ld8h(row + DINNER, gv);

        __align__(16) __half hv[8];
#pragma unroll
        for (int e = 0; e < 8; e++) {
            // exact tap order as prior rounds: x[m]*w3, x[m-1]*w2, x[m-2]*w1, x[m-3]*w0
            float a = bias[e];
            a = fmaf(xm0[e], cwv[e].w, a);
            a = fmaf(xm1[e], cwv[e].z, a);
            a = fmaf(xm2[e], cwv[e].y, a);
            a = fmaf(xm3[e], cwv[e].x, a);
            float s1 = a / (1.f + __expf(-a));
            float s2 = gv[e] / (1.f + __expf(-gv[e]));
            hv[e] = __float2half_rn(s1 * dv[e] * s2);
        }
        *reinterpret_cast<uint4*>((char*)hhi + tiled_off(m0 + step, d0, K2)) =
            *reinterpret_cast<const uint4*>(hv);

        // roll window
#pragma unroll
        for (int e = 0; e < 8; e++) { xm3[e] = xm2[e]; xm2[e] = xm1[e]; xm1[e] = xm0[e]; }
        row += N1;
    }
}

// ---------------- persistent fp16 HMMA GEMM: C[M,N] = A[M,K] * B[N,K]^T ----------------
// Grid = 148 persistent CTAs; warm 4-stage pipeline across tile boundaries.
#define TILE_BYTES  16384
#define STAGE_BYTES 32768      // A, B
#define NSTAGE      4
#define SMEM_REQ    (NSTAGE * STAGE_BYTES + 1024 + 128)

template <typename OutT>
__global__ void __launch_bounds__(288, 1)
gemm_f16(const __half* __restrict__ A, const __half* __restrict__ B,
         OutT* __restrict__ C, int M, int N, int K) {
    extern __shared__ char smem_raw[];
    uint32_t sbase = (smem_u32(smem_raw) + 1023) & ~1023u;
    const int tid = threadIdx.x, wid = tid >> 5, lane = tid & 31;
    const int KT = K >> 6;
    const int nx = N >> 7;
    const int ntiles = (M >> 7) * nx;
    const int gridsz = gridDim.x;
    const uint32_t bar = sbase + NSTAGE * STAGE_BYTES;

    if (tid == 0) {
#pragma unroll
        for (int s = 0; s < NSTAGE; s++) {
            MBAR_INIT(bar + 8 * s, 1);
            MBAR_INIT(bar + 64 + 8 * s, 8);
        }
    }
    __syncthreads();

    if (wid == 8) {
        if (lane == 0) {
            int eph[NSTAGE] = {1, 1, 1, 1};
            int s = 0;
            for (int tt = blockIdx.x; tt < ntiles; tt += gridsz) {
                const int mi = tt / nx, ni = tt % nx;
                const char* pA = (const char*)A + ((size_t)mi * KT << 14);
                const char* pB = (const char*)B + ((size_t)ni * KT << 14);
                for (int i = 0; i < KT; i++) {
                    MBAR_WAIT(bar + 64 + 8 * s, eph[s]);
                    eph[s] ^= 1;
                    MBAR_EXPECT_TX(bar + 8 * s, (uint32_t)STAGE_BYTES);
                    uint32_t st = sbase + s * STAGE_BYTES;
                    size_t ko = (size_t)i << 14;
                    BULK_G2S(st,              pA + ko, TILE_BYTES, bar + 8 * s);
                    BULK_G2S(st + TILE_BYTES, pB + ko, TILE_BYTES, bar + 8 * s);
                    if (++s == NSTAGE) s = 0;
                }
            }
        }
        return;
    }

    // ---- compute warps 0..7: warp tile 64(m) x 32(n) ----
    const int wm = wid >> 2, wn = wid & 3;

    const uint32_t msk = (uint32_t)(lane & 7) << 4;
    const uint32_t a_off0 = ((uint32_t)(wm * 64 + (lane & 15)) << 7) | (((uint32_t)lane >> 4) << 4);
    const uint32_t b_off0 = ((uint32_t)(wn * 32 + ((lane >> 4) << 3) + (lane & 7)) << 7)
                          | ((((uint32_t)lane >> 3) & 1) << 4);

    float acc[4][4][4];
#pragma unroll
    for (int i = 0; i < 4; i++)
#pragma unroll
        for (int j = 0; j < 4; j++)
#pragma unroll
            for (int e = 0; e < 4; e++) acc[i][j][e] = 0.f;

    uint32_t ah[2][4][4], bh[2][4][2];

#define LOAD_FRAGS(buf, sA, sB, ks) do {                                           \
    uint32_t _kb = (uint32_t)(ks) * 32;                                            \
    _Pragma("unroll")                                                              \
    for (int _i = 0; _i < 4; _i++)                                                 \
        ldsm_x4(ah[buf][_i], (sA) + ((a_off0 + _i * 2048 + _kb) ^ msk));           \
    _Pragma("unroll")                                                              \
    for (int _p = 0; _p < 2; _p++) {                                               \
        uint32_t _r[4];                                                            \
        ldsm_x4(_r, (sB) + ((b_off0 + _p * 2048 + _kb) ^ msk));                    \
        bh[buf][2 * _p][0] = _r[0]; bh[buf][2 * _p][1] = _r[1];                    \
        bh[buf][2 * _p + 1][0] = _r[2]; bh[buf][2 * _p + 1][1] = _r[3];            \
    } } while (0)

    int fph[NSTAGE] = {0, 0, 0, 0};
    int s = 0;
    MBAR_WAIT(bar + 0, 0);
    fph[0] ^= 1;
    uint32_t sA = sbase, sB = sbase + TILE_BYTES;
    LOAD_FRAGS(0, sA, sB, 0);

    const int g_row = lane >> 2;
    const int g_col = (lane & 3) * 2;

    for (int tt = blockIdx.x; tt < ntiles; tt += gridsz) {
        const bool last_tile = (tt + gridsz >= ntiles);
        for (int it = 0; it < KT; it++) {
            const int s2 = (s + 1 == NSTAGE) ? 0 : s + 1;
            uint32_t sA2 = sbase + s2 * STAGE_BYTES, sB2 = sA2 + TILE_BYTES;
#pragma unroll
            for (int ks = 0; ks < 4; ks++) {
                const int cur = ks & 1, nxt = cur ^ 1;
                if (ks < 3) {
                    LOAD_FRAGS(nxt, sA, sB, ks + 1);
                } else if (it + 1 < KT || !last_tile) {
                    MBAR_WAIT(bar + 8 * s2, fph[s2]);
                    fph[s2] ^= 1;
                    LOAD_FRAGS(nxt, sA2, sB2, 0);
                }
#pragma unroll
                for (int i = 0; i < 4; i++)
#pragma unroll
                    for (int j = 0; j < 4; j++)
                        mma_f16(acc[i][j], ah[cur][i], bh[cur][j]);
            }
            __syncwarp();
            if (lane == 0) MBAR_ARRIVE(bar + 64 + 8 * s);
            sA = sA2; sB = sB2;
            s = s2;
        }

        // ---- epilogue for this tile (overlaps next tile's TMA via pipeline) ----
        const int m0 = (tt / nx) * 128, n0 = (tt % nx) * 128;
#pragma unroll
        for (int i = 0; i < 4; i++) {
            size_t r0 = (size_t)m0 + wm * 64 + i * 16 + g_row;
#pragma unroll
            for (int j = 0; j < 4; j++) {
                int c = n0 + wn * 32 + j * 8 + g_col;
                if (sizeof(OutT) == 4) {
                    float2 v0 = make_float2(acc[i][j][0], acc[i][j][1]);
                    float2 v1 = make_float2(acc[i][j][2], acc[i][j][3]);
                    *reinterpret_cast<float2*>((float*)C + r0 * N + c)       = v0;
                    *reinterpret_cast<float2*>((float*)C + (r0 + 8) * N + c) = v1;
                } else {
                    __half2 v0 = __floats2half2_rn(acc[i][j][0], acc[i][j][1]);
                    __half2 v1 = __floats2half2_rn(acc[i][j][2], acc[i][j][3]);
                    *reinterpret_cast<__half2*>((__half*)C + r0 * N + c)       = v0;
                    *reinterpret_cast<__half2*>((__half*)C + (r0 + 8) * N + c) = v1;
                }
                acc[i][j][0] = 0.f; acc[i][j][1] = 0.f;
                acc[i][j][2] = 0.f; acc[i][j][3] = 0.f;
            }
        }
    }
#undef LOAD_FRAGS
}

// ---------------- launch ----------------
extern "C" void kernel_launch(void* const* d_in, const int* in_sizes, int n_in,
                              void* d_out, int out_size) {
    const float* x      = (const float*)d_in[0];
    const float* w_in   = (const float*)d_in[1];
    const float* w_out  = (const float*)d_in[2];
    const float* conv_w = (const float*)d_in[3];
    const float* conv_b = (const float*)d_in[4];
    const float* Dvec   = (const float*)d_in[5];
    float* out = (float*)d_out;

    __half *xp, *xhi, *wihi, *hhi, *wohi;
    cudaGetSymbolAddress((void**)&xp,   g_xproj);
    cudaGetSymbolAddress((void**)&xhi,  g_x_hi);
    cudaGetSymbolAddress((void**)&wihi, g_wi_hi);
    cudaGetSymbolAddress((void**)&hhi,  g_h_hi);
    cudaGetSymbolAddress((void**)&wohi, g_wo_hi);

    cudaFuncSetAttribute(gemm_f16<__half>, cudaFuncAttributeMaxDynamicSharedMemorySize, SMEM_REQ);
    cudaFuncSetAttribute(gemm_f16<float>,  cudaFuncAttributeMaxDynamicSharedMemorySize, SMEM_REQ);

    // converts (tiled+swizzled fp16)
    {
        int t8 = MTOT * K1 / 8;
        cvt_f16_tiled<<<(t8 + 255) / 256, 256>>>(x, xhi, t8, K1, 11);
    }
    {
        int t8 = N1 * K1 / 8;
        cvt_f16_tiled<<<(t8 + 255) / 256, 256>>>(w_in, wihi, t8, K1, 11);
    }
    {
        int t8 = N2 * K2 / 8;
        cvt_f16_tiled<<<(t8 + 255) / 256, 256>>>(w_out, wohi, t8, K2, 12);
    }

    // GEMM1: xproj[8192,8192] (fp16) = x @ w_in^T   (persistent)
    gemm_f16<__half><<<GRID_PERSIST, 288, SMEM_REQ>>>(xhi, wihi, xp, MTOT, N1, K1);

    // conv + gate -> h (fp16, m-walking)
    {
        int total = (MTOT / MWALK) * (DINNER / 8);
        conv_gate_f16<<<(total + 255) / 256, 256>>>(xp, conv_w, conv_b, Dvec, hhi);
    }

    // GEMM2: out[8192,2048] (fp32) = h @ w_out^T   (persistent)
    gemm_f16<float><<<GRID_PERSIST, 288, SMEM_REQ>>>(hhi, wohi, out, MTOT, N2, K2);
}

// round 17
// speedup vs baseline: 1.2382x; 1.0085x over previous
#include <cuda_runtime.h>
#include <cuda_fp16.h>
#include <stdint.h>

// Problem dims (fixed)
#define MTOT   8192     // B*T
#define SEQ    2048
#define N1     8192     // 2*d_inner
#define K1     2048     // d_model
#define DINNER 4096
#define N2     2048     // d_model
#define K2     4096     // d_inner

#define GRID_PERSIST 148
#define MWALK 16        // m-steps per conv thread (divides SEQ)

// ---------------- scratch (device globals; no runtime alloc) ----------------
__device__ __half g_xproj[(size_t)MTOT * N1];     // 128 MB (fp16)
__device__ __half g_x_hi [(size_t)MTOT * K1];
__device__ __half g_wi_hi[(size_t)N1 * K1];
__device__ __half g_h_hi [(size_t)MTOT * K2];
__device__ __half g_wo_hi[(size_t)N2 * K2];

// ---------------- PTX helpers (legal on plain sm_103) ----------------
__device__ __forceinline__ uint32_t smem_u32(const void* p) {
    uint32_t a;
    asm("{ .reg .u64 t; cvta.to.shared.u64 t, %1; cvt.u32.u64 %0, t; }" : "=r"(a) : "l"(p));
    return a;
}
#define MBAR_INIT(a, c) \
    asm volatile("mbarrier.init.shared.b64 [%0], %1;" :: "r"(a), "r"(c) : "memory")
#define MBAR_EXPECT_TX(a, b) \
    asm volatile("mbarrier.arrive.expect_tx.shared.b64 _, [%0], %1;" :: "r"(a), "r"(b) : "memory")
#define MBAR_ARRIVE(a) \
    asm volatile("mbarrier.arrive.shared.b64 _, [%0];" :: "r"(a) : "memory")
#define MBAR_WAIT(a, ph) do {                                                      \
    uint32_t _m = (a), _p = (ph), _d;                                              \
    asm volatile("{ .reg .pred p; mbarrier.try_wait.parity.acquire.cta.shared::cta.b64 p, [%1], %2;" \
                 " selp.b32 %0, 1, 0, p; }" : "=r"(_d) : "r"(_m), "r"(_p) : "memory"); \
    if (!_d) {                                                                     \
        asm volatile("{ .reg .pred P;\n"                                           \
                     "W%=: mbarrier.try_wait.parity.acquire.cta.shared::cta.b64 P, [%0], %1, 0x989680;\n" \
                     "@P bra.uni D%=;\n bra.uni W%=;\nD%=: }"                      \
                     :: "r"(_m), "r"(_p) : "memory");                              \
    } } while (0)
#define BULK_G2S(sa, gp, bytes, mb) \
    asm volatile("cp.async.bulk.shared::cluster.global.mbarrier::complete_tx::bytes [%0], [%1], %2, [%3];" \
                 :: "r"(sa), "l"(gp), "r"(bytes), "r"(mb) : "memory")

__device__ __forceinline__ void ldsm_x4(uint32_t* r, uint32_t addr) {
    asm volatile("ldmatrix.sync.aligned.m8n8.x4.shared.b16 {%0,%1,%2,%3}, [%4];"
                 : "=r"(r[0]), "=r"(r[1]), "=r"(r[2]), "=r"(r[3]) : "r"(addr));
}
__device__ __forceinline__ void mma_f16(float* d, const uint32_t* a, const uint32_t* b) {
    asm volatile("mma.sync.aligned.m16n8k16.row.col.f32.f16.f16.f32 "
                 "{%0,%1,%2,%3},{%4,%5,%6,%7},{%8,%9},{%0,%1,%2,%3};"
                 : "+f"(d[0]), "+f"(d[1]), "+f"(d[2]), "+f"(d[3])
                 : "r"(a[0]), "r"(a[1]), "r"(a[2]), "r"(a[3]), "r"(b[0]), "r"(b[1]));
}

// fp16 tiled layout: 128 rows x 64 fp16 (16 KB) tiles, k-tile fastest, SW128 swizzle.
__device__ __forceinline__ size_t tiled_off(int r, int c, int K) {
    size_t tile = ((size_t)(r >> 7) * (size_t)(K >> 6) + (size_t)(c >> 6)) << 14;
    uint32_t off = ((uint32_t)(r & 127) << 7) | ((uint32_t)(c & 63) << 1);
    off ^= (off >> 3) & 0x70;
    return tile + off;
}

// ---------------- fused fp32 -> fp16 tiled conversion (x, w_in, w_out in one grid) ----
__device__ __forceinline__ void cvt8(const float* __restrict__ src, __half* __restrict__ dst,
                                     int idx, int K, int kshift) {
    int e0 = idx << 3;
    int r = e0 >> kshift;
    int c = e0 & (K - 1);
    const float* p = src + (size_t)r * K + c;
    float4 v0 = *reinterpret_cast<const float4*>(p);
    float4 v1 = *reinterpret_cast<const float4*>(p + 4);
    float xs[8] = {v0.x, v0.y, v0.z, v0.w, v1.x, v1.y, v1.z, v1.w};
    __align__(16) __half hv[8];
#pragma unroll
    for (int j = 0; j < 8; j++) hv[j] = __float2half_rn(xs[j]);
    *reinterpret_cast<uint4*>((char*)dst + tiled_off(r, c, K)) = *reinterpret_cast<const uint4*>(hv);
}

#define T8_X  (MTOT * K1 / 8)     // 2M
#define T8_WI (N1 * K1 / 8)       // 2M
#define T8_WO (N2 * K2 / 8)       // 1M

__global__ void cvt_all_f16(const float* __restrict__ x,   __half* __restrict__ xhi,
                            const float* __restrict__ wi,  __half* __restrict__ wihi,
                            const float* __restrict__ wo,  __half* __restrict__ wohi) {
    int idx = blockIdx.x * blockDim.x + threadIdx.x;
    if (idx < T8_X) {
        cvt8(x, xhi, idx, K1, 11);
    } else if (idx < T8_X + T8_WI) {
        cvt8(wi, wihi, idx - T8_X, K1, 11);
    } else if (idx < T8_X + T8_WI + T8_WO) {
        cvt8(wo, wohi, idx - T8_X - T8_WI, K2, 12);
    }
}

// ------- depthwise causal conv(4) + SiLU gate (fp16 xproj in) -> fp16 tiled -------
// m-WALKING: each thread keeps 8 channels and walks MWALK consecutive m values.
__device__ __forceinline__ void ld8h(const __half* p, float* out) {
    uint4 raw = *reinterpret_cast<const uint4*>(p);
    const __half2* hp = reinterpret_cast<const __half2*>(&raw);
#pragma unroll
    for (int q = 0; q < 4; q++) {
        float2 f = __half22float2(hp[q]);
        out[2 * q] = f.x; out[2 * q + 1] = f.y;
    }
}

__global__ void conv_gate_f16(const __half* __restrict__ xp, const float* __restrict__ cw,
                              const float* __restrict__ cb, const float* __restrict__ Dv,
                              __half* __restrict__ hhi) {
    int idx = blockIdx.x * blockDim.x + threadIdx.x;
    if (idx >= (MTOT / MWALK) * (DINNER / 8)) return;
    const int d0 = (idx & 511) << 3;          // 8-channel group (DINNER/8 = 512)
    const int m0 = (idx >> 9) * MWALK;        // walk start (multiple of 16; SEQ%16==0)
    const int t0 = m0 & (SEQ - 1);
    const __half* row = xp + (size_t)m0 * N1 + d0;

    float4 cwv[8];
#pragma unroll
    for (int e = 0; e < 8; e++) cwv[e] = *reinterpret_cast<const float4*>(cw + (size_t)(d0 + e) * 4);
    float4 b0 = *reinterpret_cast<const float4*>(cb + d0);
    float4 b1 = *reinterpret_cast<const float4*>(cb + d0 + 4);
    float bias[8] = {b0.x, b0.y, b0.z, b0.w, b1.x, b1.y, b1.z, b1.w};
    float4 dv0 = *reinterpret_cast<const float4*>(Dv + d0);
    float4 dv1 = *reinterpret_cast<const float4*>(Dv + d0 + 4);
    float dv[8] = {dv0.x, dv0.y, dv0.z, dv0.w, dv1.x, dv1.y, dv1.z, dv1.w};

    float xm1[8] = {0,0,0,0,0,0,0,0};
    float xm2[8] = {0,0,0,0,0,0,0,0};
    float xm3[8] = {0,0,0,0,0,0,0,0};
    if (t0 >= 1) ld8h(row - (size_t)1 * N1, xm1);
    if (t0 >= 2) ld8h(row - (size_t)2 * N1, xm2);
    if (t0 >= 3) ld8h(row - (size_t)3 * N1, xm3);

#pragma unroll 4
    for (int step = 0; step < MWALK; step++) {
        float xm0[8], gv[8];
        ld8h(row, xm0);
        ld8h(row + DINNER, gv);

        __align__(16) __half hv[8];
#pragma unroll
        for (int e = 0; e < 8; e++) {
            float a = bias[e];
            a = fmaf(xm0[e], cwv[e].w, a);
            a = fmaf(xm1[e], cwv[e].z, a);
            a = fmaf(xm2[e], cwv[e].y, a);
            a = fmaf(xm3[e], cwv[e].x, a);
            float s1 = a / (1.f + __expf(-a));
            float s2 = gv[e] / (1.f + __expf(-gv[e]));
            hv[e] = __float2half_rn(s1 * dv[e] * s2);
        }
        *reinterpret_cast<uint4*>((char*)hhi + tiled_off(m0 + step, d0, K2)) =
            *reinterpret_cast<const uint4*>(hv);

#pragma unroll
        for (int e = 0; e < 8; e++) { xm3[e] = xm2[e]; xm2[e] = xm1[e]; xm1[e] = xm0[e]; }
        row += N1;
    }
}

// ---------------- persistent fp16 HMMA GEMM: C[M,N] = A[M,K] * B[N,K]^T ----------------
// Grid = 148 persistent CTAs; warm 4-stage pipeline across tile boundaries.
#define TILE_BYTES  16384
#define STAGE_BYTES 32768      // A, B
#define NSTAGE      4
#define SMEM_REQ    (NSTAGE * STAGE_BYTES + 1024 + 128)

template <typename OutT>
__global__ void __launch_bounds__(288, 1)
gemm_f16(const __half* __restrict__ A, const __half* __restrict__ B,
         OutT* __restrict__ C, int M, int N, int K) {
    extern __shared__ char smem_raw[];
    uint32_t sbase = (smem_u32(smem_raw) + 1023) & ~1023u;
    const int tid = threadIdx.x, wid = tid >> 5, lane = tid & 31;
    const int KT = K >> 6;
    const int nx = N >> 7;
    const int ntiles = (M >> 7) * nx;
    const int gridsz = gridDim.x;
    const uint32_t bar = sbase + NSTAGE * STAGE_BYTES;

    if (tid == 0) {
#pragma unroll
        for (int s = 0; s < NSTAGE; s++) {
            MBAR_INIT(bar + 8 * s, 1);
            MBAR_INIT(bar + 64 + 8 * s, 8);
        }
    }
    __syncthreads();

    if (wid == 8) {
        if (lane == 0) {
            int eph[NSTAGE] = {1, 1, 1, 1};
            int s = 0;
            for (int tt = blockIdx.x; tt < ntiles; tt += gridsz) {
                const int mi = tt / nx, ni = tt % nx;
                const char* pA = (const char*)A + ((size_t)mi * KT << 14);
                const char* pB = (const char*)B + ((size_t)ni * KT << 14);
                for (int i = 0; i < KT; i++) {
                    MBAR_WAIT(bar + 64 + 8 * s, eph[s]);
                    eph[s] ^= 1;
                    MBAR_EXPECT_TX(bar + 8 * s, (uint32_t)STAGE_BYTES);
                    uint32_t st = sbase + s * STAGE_BYTES;
                    size_t ko = (size_t)i << 14;
                    BULK_G2S(st,              pA + ko, TILE_BYTES, bar + 8 * s);
                    BULK_G2S(st + TILE_BYTES, pB + ko, TILE_BYTES, bar + 8 * s);
                    if (++s == NSTAGE) s = 0;
                }
            }
        }
        return;
    }

    // ---- compute warps 0..7: warp tile 64(m) x 32(n) ----
    const int wm = wid >> 2, wn = wid & 3;

    const uint32_t msk = (uint32_t)(lane & 7) << 4;
    const uint32_t a_off0 = ((uint32_t)(wm * 64 + (lane & 15)) << 7) | (((uint32_t)lane >> 4) << 4);
    const uint32_t b_off0 = ((uint32_t)(wn * 32 + ((lane >> 4) << 3) + (lane & 7)) << 7)
                          | ((((uint32_t)lane >> 3) & 1) << 4);

    float acc[4][4][4];
#pragma unroll
    for (int i = 0; i < 4; i++)
#pragma unroll
        for (int j = 0; j < 4; j++)
#pragma unroll
            for (int e = 0; e < 4; e++) acc[i][j][e] = 0.f;

    uint32_t ah[2][4][4], bh[2][4][2];

#define LOAD_FRAGS(buf, sA, sB, ks) do {                                           \
    uint32_t _kb = (uint32_t)(ks) * 32;                                            \
    _Pragma("unroll")                                                              \
    for (int _i = 0; _i < 4; _i++)                                                 \
        ldsm_x4(ah[buf][_i], (sA) + ((a_off0 + _i * 2048 + _kb) ^ msk));           \
    _Pragma("unroll")                                                              \
    for (int _p = 0; _p < 2; _p++) {                                               \
        uint32_t _r[4];                                                            \
        ldsm_x4(_r, (sB) + ((b_off0 + _p * 2048 + _kb) ^ msk));                    \
        bh[buf][2 * _p][0] = _r[0]; bh[buf][2 * _p][1] = _r[1];                    \
        bh[buf][2 * _p + 1][0] = _r[2]; bh[buf][2 * _p + 1][1] = _r[3];            \
    } } while (0)

    int fph[NSTAGE] = {0, 0, 0, 0};
    int s = 0;
    MBAR_WAIT(bar + 0, 0);
    fph[0] ^= 1;
    uint32_t sA = sbase, sB = sbase + TILE_BYTES;
    LOAD_FRAGS(0, sA, sB, 0);

    const int g_row = lane >> 2;
    const int g_col = (lane & 3) * 2;

    for (int tt = blockIdx.x; tt < ntiles; tt += gridsz) {
        const bool last_tile = (tt + gridsz >= ntiles);
        for (int it = 0; it < KT; it++) {
            const int s2 = (s + 1 == NSTAGE) ? 0 : s + 1;
            uint32_t sA2 = sbase + s2 * STAGE_BYTES, sB2 = sA2 + TILE_BYTES;
#pragma unroll
            for (int ks = 0; ks < 4; ks++) {
                const int cur = ks & 1, nxt = cur ^ 1;
                if (ks < 3) {
                    LOAD_FRAGS(nxt, sA, sB, ks + 1);
                } else if (it + 1 < KT || !last_tile) {
                    MBAR_WAIT(bar + 8 * s2, fph[s2]);
                    fph[s2] ^= 1;
                    LOAD_FRAGS(nxt, sA2, sB2, 0);
                }
#pragma unroll
                for (int i = 0; i < 4; i++)
#pragma unroll
                    for (int j = 0; j < 4; j++)
                        mma_f16(acc[i][j], ah[cur][i], bh[cur][j]);
            }
            __syncwarp();
            if (lane == 0) MBAR_ARRIVE(bar + 64 + 8 * s);
            sA = sA2; sB = sB2;
            s = s2;
        }

        // ---- epilogue for this tile (overlaps next tile's TMA via pipeline) ----
        const int m0 = (tt / nx) * 128, n0 = (tt % nx) * 128;
#pragma unroll
        for (int i = 0; i < 4; i++) {
            size_t r0 = (size_t)m0 + wm * 64 + i * 16 + g_row;
#pragma unroll
            for (int j = 0; j < 4; j++) {
                int c = n0 + wn * 32 + j * 8 + g_col;
                if (sizeof(OutT) == 4) {
                    float2 v0 = make_float2(acc[i][j][0], acc[i][j][1]);
                    float2 v1 = make_float2(acc[i][j][2], acc[i][j][3]);
                    *reinterpret_cast<float2*>((float*)C + r0 * N + c)       = v0;
                    *reinterpret_cast<float2*>((float*)C + (r0 + 8) * N + c) = v1;
                } else {
                    __half2 v0 = __floats2half2_rn(acc[i][j][0], acc[i][j][1]);
                    __half2 v1 = __floats2half2_rn(acc[i][j][2], acc[i][j][3]);
                    *reinterpret_cast<__half2*>((__half*)C + r0 * N + c)       = v0;
                    *reinterpret_cast<__half2*>((__half*)C + (r0 + 8) * N + c) = v1;
                }
                acc[i][j][0] = 0.f; acc[i][j][1] = 0.f;
                acc[i][j][2] = 0.f; acc[i][j][3] = 0.f;
            }
        }
    }
#undef LOAD_FRAGS
}

// ---------------- launch ----------------
extern "C" void kernel_launch(void* const* d_in, const int* in_sizes, int n_in,
                              void* d_out, int out_size) {
    const float* x      = (const float*)d_in[0];
    const float* w_in   = (const float*)d_in[1];
    const float* w_out  = (const float*)d_in[2];
    const float* conv_w = (const float*)d_in[3];
    const float* conv_b = (const float*)d_in[4];
    const float* Dvec   = (const float*)d_in[5];
    float* out = (float*)d_out;

    __half *xp, *xhi, *wihi, *hhi, *wohi;
    cudaGetSymbolAddress((void**)&xp,   g_xproj);
    cudaGetSymbolAddress((void**)&xhi,  g_x_hi);
    cudaGetSymbolAddress((void**)&wihi, g_wi_hi);
    cudaGetSymbolAddress((void**)&hhi,  g_h_hi);
    cudaGetSymbolAddress((void**)&wohi, g_wo_hi);

    cudaFuncSetAttribute(gemm_f16<__half>, cudaFuncAttributeMaxDynamicSharedMemorySize, SMEM_REQ);
    cudaFuncSetAttribute(gemm_f16<float>,  cudaFuncAttributeMaxDynamicSharedMemorySize, SMEM_REQ);

    // fused converts (x, w_in, w_out) — single launch
    {
        int total = T8_X + T8_WI + T8_WO;
        cvt_all_f16<<<(total + 255) / 256, 256>>>(x, xhi, w_in, wihi, w_out, wohi);
    }

    // GEMM1: xproj[8192,8192] (fp16) = x @ w_in^T   (persistent)
    gemm_f16<__half><<<GRID_PERSIST, 288, SMEM_REQ>>>(xhi, wihi, xp, MTOT, N1, K1);

    // conv + gate -> h (fp16, m-walking)
    {
        int total = (MTOT / MWALK) * (DINNER / 8);
        conv_gate_f16<<<(total + 255) / 256, 256>>>(xp, conv_w, conv_b, Dvec, hhi);
    }

    // GEMM2: out[8192,2048] (fp32) = h @ w_out^T   (persistent)
    gemm_f16<float><<<GRID_PERSIST, 288, SMEM_REQ>>>(hhi, wohi, out, MTOT, N2, K2);
}